// round 1
// baseline (speedup 1.0000x reference)
#include <cuda_runtime.h>
#include <cuda_bf16.h>
#include <math.h>

#define NV 150000
#define NFACE 300000
#define L0 192
#define L1 96
#define L2DIM 48
#define KC 384            // padded conv K (375 -> 384)

// ---------------- scratch (device globals; no allocation allowed) ----------
__device__ float g_nrm[NV * 3];
__device__ float g_vol1[L1 * L1 * L1];
__device__ float g_vol2[L2DIM * L2DIM * L2DIM];
__device__ float g_convT[KC * 128];
__device__ float g_cubes[(size_t)NV * KC];
__device__ float g_xcat[(size_t)NV * 256];
__device__ float g_xl0[(size_t)NV * 128];
__device__ float g_h2[(size_t)NV * 512];
__device__ float g_h3[(size_t)NV * 256];

// ---------------- small kernels --------------------------------------------
__global__ void k_zero(float* p, int n) {
    int i = blockIdx.x * blockDim.x + threadIdx.x;
    if (i < n) p[i] = 0.f;
}

__global__ void k_face_normals(const float* __restrict__ v, const int* __restrict__ f) {
    int i = blockIdx.x * blockDim.x + threadIdx.x;
    if (i >= NFACE) return;
    int i0 = f[i * 3 + 0], i1 = f[i * 3 + 1], i2 = f[i * 3 + 2];
    float p0x = v[i0 * 3], p0y = v[i0 * 3 + 1], p0z = v[i0 * 3 + 2];
    float p1x = v[i1 * 3], p1y = v[i1 * 3 + 1], p1z = v[i1 * 3 + 2];
    float p2x = v[i2 * 3], p2y = v[i2 * 3 + 1], p2z = v[i2 * 3 + 2];
    float ax = p1x - p0x, ay = p1y - p0y, az = p1z - p0z;
    float bx = p2x - p0x, by = p2y - p0y, bz = p2z - p0z;
    float cx = ay * bz - az * by;
    float cy = az * bx - ax * bz;
    float cz = ax * by - ay * bx;
    atomicAdd(&g_nrm[i0 * 3 + 0], cx); atomicAdd(&g_nrm[i0 * 3 + 1], cy); atomicAdd(&g_nrm[i0 * 3 + 2], cz);
    atomicAdd(&g_nrm[i1 * 3 + 0], cx); atomicAdd(&g_nrm[i1 * 3 + 1], cy); atomicAdd(&g_nrm[i1 * 3 + 2], cz);
    atomicAdd(&g_nrm[i2 * 3 + 0], cx); atomicAdd(&g_nrm[i2 * 3 + 1], cy); atomicAdd(&g_nrm[i2 * 3 + 2], cz);
}

// avgpool-2 downsample: dst[s^3] from src[(2s)^3]
__global__ void k_down(const float* __restrict__ src, float* __restrict__ dst, int s) {
    int i = blockIdx.x * blockDim.x + threadIdx.x;
    int tot = s * s * s;
    if (i >= tot) return;
    int c = i % s, b = (i / s) % s, a = i / (s * s);
    int S = 2 * s;
    float sum = 0.f;
#pragma unroll
    for (int da = 0; da < 2; da++)
#pragma unroll
        for (int db = 0; db < 2; db++)
#pragma unroll
            for (int dc = 0; dc < 2; dc++)
                sum += src[((size_t)(2 * a + da) * S + (2 * b + db)) * S + (2 * c + dc)];
    dst[i] = sum * 0.125f;
}

// transpose conv_w [128][375] -> g_convT [384][128] (zero-padded rows >= 375)
__global__ void k_convT(const float* __restrict__ w) {
    int i = blockIdx.x * blockDim.x + threadIdx.x;
    if (i >= KC * 128) return;
    int o = i % 128, c = i / 128;
    g_convT[i] = (c < 375) ? w[o * 375 + c] : 0.f;
}

// per-vertex: normalize normal, fc1 (6->128) + leaky, write xcat[:,0:128]
__global__ void k_fc1(const float* __restrict__ v, const float* __restrict__ w,
                      const float* __restrict__ b) {
    int vid = blockIdx.x;
    int o = threadIdx.x;  // 128
    float in0 = v[vid * 3 + 0], in1 = v[vid * 3 + 1], in2 = v[vid * 3 + 2];
    float nx = g_nrm[vid * 3 + 0], ny = g_nrm[vid * 3 + 1], nz = g_nrm[vid * 3 + 2];
    float nn = fmaxf(sqrtf(nx * nx + ny * ny + nz * nz), 1e-12f);
    float in3 = nx / nn, in4 = ny / nn, in5 = nz / nn;
    float acc = b[o];
    acc += in0 * w[0 * 128 + o];
    acc += in1 * w[1 * 128 + o];
    acc += in2 * w[2 * 128 + o];
    acc += in3 * w[3 * 128 + o];
    acc += in4 * w[4 * 128 + o];
    acc += in5 * w[5 * 128 + o];
    g_xcat[(size_t)vid * 256 + o] = acc > 0.f ? acc : 0.15f * acc;
}

// gather 3-scale 5x5x5 cubes into g_cubes[v][384]
__global__ void k_gather(const float* __restrict__ v, const float* __restrict__ vol0) {
    int vid = blockIdx.x;
    float vx = v[vid * 3 + 0], vy = v[vid * 3 + 1], vz = v[vid * 3 + 2];
    for (int c = threadIdx.x; c < KC; c += blockDim.x) {
        float val = 0.f;
        if (c < 375) {
            int n = c / 125, r = c % 125;
            int di = r / 25, dj = (r / 5) % 5, dk = r % 5;
            const float* vol;
            int dim;
            float scale;
            if (n == 0)      { vol = vol0;   dim = L0;    scale = 96.f; }
            else if (n == 1) { vol = g_vol1; dim = L1;    scale = 48.f; }
            else             { vol = g_vol2; dim = L2DIM; scale = 24.f; }
            int hi = dim - 3;
            int i0 = min(max((int)rintf((vx + 1.f) * scale), 2), hi) + di - 2;
            int i1 = min(max((int)rintf((vy + 1.f) * scale), 2), hi) + dj - 2;
            int i2 = min(max((int)rintf((vz + 1.f) * scale), 2), hi) + dk - 2;
            val = vol[((size_t)i0 * dim + i1) * dim + i2];
        }
        g_cubes[(size_t)vid * KC + c] = val;
    }
}

// ---------------- tiled fp32 GEMM: C = act(A*B + bias) ---------------------
// BM=128, BN=64, BK=16, 256 threads, 8x4 register tile.
// A: M x Kd (row-major, leading dim lda), B: Kd x N (row-major, dense),
// C: M x N (leading dim ldc). ACT: 0 = none, 1 = leaky_relu(0.15)
template <int ACT>
__global__ void gemm_k(const float* __restrict__ A, const float* __restrict__ B,
                       const float* __restrict__ bias, float* __restrict__ C,
                       int M, int N, int Kd, int lda, int ldc) {
    __shared__ float As[16][132];
    __shared__ float Bs[16][64];
    const int t = threadIdx.x;
    const int bm = blockIdx.y * 128;
    const int bn = blockIdx.x * 64;
    const int tx = t & 15;   // n group (0..15)
    const int ty = t >> 4;   // m group (0..15)

    float acc[8][4];
#pragma unroll
    for (int i = 0; i < 8; i++)
#pragma unroll
        for (int j = 0; j < 4; j++) acc[i][j] = 0.f;

    for (int k0 = 0; k0 < Kd; k0 += 16) {
        // load A tile (128x16) as 512 float4s, 2 per thread
#pragma unroll
        for (int li = 0; li < 2; li++) {
            int e = t + li * 256;
            int row = e >> 2;
            int kv = e & 3;
            float4 av = make_float4(0.f, 0.f, 0.f, 0.f);
            int gm = bm + row;
            if (gm < M)
                av = *reinterpret_cast<const float4*>(A + (size_t)gm * lda + k0 + kv * 4);
            As[kv * 4 + 0][row] = av.x;
            As[kv * 4 + 1][row] = av.y;
            As[kv * 4 + 2][row] = av.z;
            As[kv * 4 + 3][row] = av.w;
        }
        // load B tile (16x64) as 256 float4s, 1 per thread
        {
            int row = t >> 4;
            int col4 = t & 15;
            float4 bv = *reinterpret_cast<const float4*>(B + (size_t)(k0 + row) * N + bn + col4 * 4);
            *reinterpret_cast<float4*>(&Bs[row][col4 * 4]) = bv;
        }
        __syncthreads();
#pragma unroll
        for (int kk = 0; kk < 16; kk++) {
            float a[8], b[4];
#pragma unroll
            for (int i = 0; i < 8; i++) a[i] = As[kk][ty * 8 + i];
#pragma unroll
            for (int j = 0; j < 4; j++) b[j] = Bs[kk][tx * 4 + j];
#pragma unroll
            for (int i = 0; i < 8; i++)
#pragma unroll
                for (int j = 0; j < 4; j++) acc[i][j] += a[i] * b[j];
        }
        __syncthreads();
    }
#pragma unroll
    for (int i = 0; i < 8; i++) {
        int gm = bm + ty * 8 + i;
        if (gm >= M) continue;
#pragma unroll
        for (int j = 0; j < 4; j++) {
            int gn = bn + tx * 4 + j;
            float val = acc[i][j] + bias[gn];
            if (ACT == 1) val = val > 0.f ? val : 0.15f * val;
            C[(size_t)gm * ldc + gn] = val;
        }
    }
}

// fc4: 256 -> 3, tanh * 0.1, + coord. One warp per vertex.
__global__ void k_fc4(const float* __restrict__ v, const float* __restrict__ w,
                      const float* __restrict__ b, float* __restrict__ out) {
    int gtid = blockIdx.x * blockDim.x + threadIdx.x;
    int vert = gtid >> 5;
    int lane = threadIdx.x & 31;
    if (vert >= NV) return;
    const float* h = g_h3 + (size_t)vert * 256;
    float s0 = 0.f, s1 = 0.f, s2 = 0.f;
#pragma unroll
    for (int i = 0; i < 8; i++) {
        int k = lane + i * 32;
        float x = h[k];
        s0 += x * w[k * 3 + 0];
        s1 += x * w[k * 3 + 1];
        s2 += x * w[k * 3 + 2];
    }
#pragma unroll
    for (int off = 16; off > 0; off >>= 1) {
        s0 += __shfl_down_sync(0xFFFFFFFFu, s0, off);
        s1 += __shfl_down_sync(0xFFFFFFFFu, s1, off);
        s2 += __shfl_down_sync(0xFFFFFFFFu, s2, off);
    }
    if (lane == 0) {
        out[vert * 3 + 0] = v[vert * 3 + 0] + 0.1f * tanhf(s0 + b[0]);
        out[vert * 3 + 1] = v[vert * 3 + 1] + 0.1f * tanhf(s1 + b[1]);
        out[vert * 3 + 2] = v[vert * 3 + 2] + 0.1f * tanhf(s2 + b[2]);
    }
}

// ---------------- launch ----------------------------------------------------
extern "C" void kernel_launch(void* const* d_in, const int* in_sizes, int n_in,
                              void* d_out, int out_size) {
    const float* v      = (const float*)d_in[0];
    const int*   f      = (const int*)d_in[1];
    const float* volume = (const float*)d_in[2];
    const float* fc1_w  = (const float*)d_in[3];
    const float* fc1_b  = (const float*)d_in[4];
    const float* fc2_w  = (const float*)d_in[5];
    const float* fc2_b  = (const float*)d_in[6];
    const float* fc3_w  = (const float*)d_in[7];
    const float* fc3_b  = (const float*)d_in[8];
    const float* fc4_w  = (const float*)d_in[9];
    const float* fc4_b  = (const float*)d_in[10];
    const float* conv_w = (const float*)d_in[11];
    const float* conv_b = (const float*)d_in[12];
    const float* lfc_w  = (const float*)d_in[13];
    const float* lfc_b  = (const float*)d_in[14];
    float* out = (float*)d_out;

    float *p_nrm, *p_vol1, *p_vol2, *p_cubes, *p_xcat, *p_xl0, *p_h2, *p_h3, *p_convT;
    cudaGetSymbolAddress((void**)&p_nrm, g_nrm);
    cudaGetSymbolAddress((void**)&p_vol1, g_vol1);
    cudaGetSymbolAddress((void**)&p_vol2, g_vol2);
    cudaGetSymbolAddress((void**)&p_cubes, g_cubes);
    cudaGetSymbolAddress((void**)&p_xcat, g_xcat);
    cudaGetSymbolAddress((void**)&p_xl0, g_xl0);
    cudaGetSymbolAddress((void**)&p_h2, g_h2);
    cudaGetSymbolAddress((void**)&p_h3, g_h3);
    cudaGetSymbolAddress((void**)&p_convT, g_convT);

    // 1. normals: zero + scatter
    k_zero<<<(NV * 3 + 255) / 256, 256>>>(p_nrm, NV * 3);
    k_face_normals<<<(NFACE + 255) / 256, 256>>>(v, f);

    // 2. volume pyramid
    k_down<<<(L1 * L1 * L1 + 255) / 256, 256>>>(volume, p_vol1, L1);
    k_down<<<(L2DIM * L2DIM * L2DIM + 255) / 256, 256>>>(p_vol1, p_vol2, L2DIM);

    // 3. conv weight transpose (375x128, padded to 384)
    k_convT<<<(KC * 128 + 255) / 256, 256>>>(conv_w);

    // 4. fc1 (+normal normalize) -> xcat[:, 0:128]
    k_fc1<<<NV, 128>>>(v, fc1_w, fc1_b);

    // 5. cube gather -> g_cubes [NV x 384]
    k_gather<<<NV, 128>>>(v, volume);

    const int MB = (NV + 127) / 128;

    // 6. conv einsum: cubes[NV,384] x convT[384,128] + conv_b -> xl0
    gemm_k<0><<<dim3(128 / 64, MB), 256>>>(p_cubes, p_convT, conv_b, p_xl0,
                                           NV, 128, KC, KC, 128);

    // 7. lfc: xl0[NV,128] x lfc_w[128,128] + lfc_b -> xcat[:, 128:256]
    gemm_k<0><<<dim3(128 / 64, MB), 256>>>(p_xl0, lfc_w, lfc_b, p_xcat + 128,
                                           NV, 128, 128, 128, 256);

    // 8. fc2: xcat[NV,256] x fc2_w[256,512] + b, leaky -> h2
    gemm_k<1><<<dim3(512 / 64, MB), 256>>>(p_xcat, fc2_w, fc2_b, p_h2,
                                           NV, 512, 256, 256, 512);

    // 9. fc3: h2[NV,512] x fc3_w[512,256] + b, leaky -> h3
    gemm_k<1><<<dim3(256 / 64, MB), 256>>>(p_h2, fc3_w, fc3_b, p_h3,
                                           NV, 256, 512, 512, 256);

    // 10. fc4 + tanh*0.1 + coord
    k_fc4<<<(NV * 32 + 255) / 256, 256>>>(v, fc4_w, fc4_b, out);
}

// round 3
// speedup vs baseline: 1.5177x; 1.5177x over previous
#include <cuda_runtime.h>
#include <cuda_bf16.h>
#include <cstdint>
#include <math.h>

#define NV 150000
#define NFACE 300000
#define L0 192
#define L1 96
#define L2DIM 48
#define KC 384            // padded conv K (375 -> 384)

// ---------------- scratch (device globals; no allocation allowed) ----------
__device__ float g_nrm[NV * 3];
__device__ float g_vol1[L1 * L1 * L1];
__device__ float g_vol2[L2DIM * L2DIM * L2DIM];
__device__ float g_convT[KC * 128];
__device__ float g_cubes[(size_t)NV * KC];
__device__ float g_xcat[(size_t)NV * 256];
__device__ float g_xl0[(size_t)NV * 128];
__device__ float g_h2[(size_t)NV * 512];
__device__ float g_h3[(size_t)NV * 256];

// ---------------- small kernels --------------------------------------------
__global__ void k_zero(float* p, int n) {
    int i = blockIdx.x * blockDim.x + threadIdx.x;
    if (i < n) p[i] = 0.f;
}

__global__ void k_face_normals(const float* __restrict__ v, const int* __restrict__ f) {
    int i = blockIdx.x * blockDim.x + threadIdx.x;
    if (i >= NFACE) return;
    int i0 = f[i * 3 + 0], i1 = f[i * 3 + 1], i2 = f[i * 3 + 2];
    float p0x = v[i0 * 3], p0y = v[i0 * 3 + 1], p0z = v[i0 * 3 + 2];
    float p1x = v[i1 * 3], p1y = v[i1 * 3 + 1], p1z = v[i1 * 3 + 2];
    float p2x = v[i2 * 3], p2y = v[i2 * 3 + 1], p2z = v[i2 * 3 + 2];
    float ax = p1x - p0x, ay = p1y - p0y, az = p1z - p0z;
    float bx = p2x - p0x, by = p2y - p0y, bz = p2z - p0z;
    float cx = ay * bz - az * by;
    float cy = az * bx - ax * bz;
    float cz = ax * by - ay * bx;
    atomicAdd(&g_nrm[i0 * 3 + 0], cx); atomicAdd(&g_nrm[i0 * 3 + 1], cy); atomicAdd(&g_nrm[i0 * 3 + 2], cz);
    atomicAdd(&g_nrm[i1 * 3 + 0], cx); atomicAdd(&g_nrm[i1 * 3 + 1], cy); atomicAdd(&g_nrm[i1 * 3 + 2], cz);
    atomicAdd(&g_nrm[i2 * 3 + 0], cx); atomicAdd(&g_nrm[i2 * 3 + 1], cy); atomicAdd(&g_nrm[i2 * 3 + 2], cz);
}

// avgpool-2 downsample: dst[s^3] from src[(2s)^3]
__global__ void k_down(const float* __restrict__ src, float* __restrict__ dst, int s) {
    int i = blockIdx.x * blockDim.x + threadIdx.x;
    int tot = s * s * s;
    if (i >= tot) return;
    int c = i % s, b = (i / s) % s, a = i / (s * s);
    int S = 2 * s;
    float sum = 0.f;
#pragma unroll
    for (int da = 0; da < 2; da++)
#pragma unroll
        for (int db = 0; db < 2; db++)
#pragma unroll
            for (int dc = 0; dc < 2; dc++)
                sum += src[((size_t)(2 * a + da) * S + (2 * b + db)) * S + (2 * c + dc)];
    dst[i] = sum * 0.125f;
}

// transpose conv_w [128][375] -> g_convT [384][128] (zero-padded rows >= 375)
__global__ void k_convT(const float* __restrict__ w) {
    int i = blockIdx.x * blockDim.x + threadIdx.x;
    if (i >= KC * 128) return;
    int o = i % 128, c = i / 128;
    g_convT[i] = (c < 375) ? w[o * 375 + c] : 0.f;
}

// per-vertex: normalize normal, fc1 (6->128) + leaky, write xcat[:,0:128]
__global__ void k_fc1(const float* __restrict__ v, const float* __restrict__ w,
                      const float* __restrict__ b) {
    int vid = blockIdx.x;
    int o = threadIdx.x;  // 128
    float in0 = v[vid * 3 + 0], in1 = v[vid * 3 + 1], in2 = v[vid * 3 + 2];
    float nx = g_nrm[vid * 3 + 0], ny = g_nrm[vid * 3 + 1], nz = g_nrm[vid * 3 + 2];
    float nn = fmaxf(sqrtf(nx * nx + ny * ny + nz * nz), 1e-12f);
    float in3 = nx / nn, in4 = ny / nn, in5 = nz / nn;
    float acc = b[o];
    acc += in0 * w[0 * 128 + o];
    acc += in1 * w[1 * 128 + o];
    acc += in2 * w[2 * 128 + o];
    acc += in3 * w[3 * 128 + o];
    acc += in4 * w[4 * 128 + o];
    acc += in5 * w[5 * 128 + o];
    g_xcat[(size_t)vid * 256 + o] = acc > 0.f ? acc : 0.15f * acc;
}

// gather 3-scale 5x5x5 cubes into g_cubes[v][384]
__global__ void k_gather(const float* __restrict__ v, const float* __restrict__ vol0) {
    int vid = blockIdx.x;
    float vx = v[vid * 3 + 0], vy = v[vid * 3 + 1], vz = v[vid * 3 + 2];
    for (int c = threadIdx.x; c < KC; c += blockDim.x) {
        float val = 0.f;
        if (c < 375) {
            int n = c / 125, r = c % 125;
            int di = r / 25, dj = (r / 5) % 5, dk = r % 5;
            const float* vol;
            int dim;
            float scale;
            if (n == 0)      { vol = vol0;   dim = L0;    scale = 96.f; }
            else if (n == 1) { vol = g_vol1; dim = L1;    scale = 48.f; }
            else             { vol = g_vol2; dim = L2DIM; scale = 24.f; }
            int hi = dim - 3;
            int i0 = min(max((int)rintf((vx + 1.f) * scale), 2), hi) + di - 2;
            int i1 = min(max((int)rintf((vy + 1.f) * scale), 2), hi) + dj - 2;
            int i2 = min(max((int)rintf((vz + 1.f) * scale), 2), hi) + dk - 2;
            val = vol[((size_t)i0 * dim + i1) * dim + i2];
        }
        g_cubes[(size_t)vid * KC + c] = val;
    }
}

// ---------------- tf32 tensor-core GEMM -------------------------------------
// C = act(A*B + bias). Block tile 128x128, warp tile 64x32, BK=32, 256 thr.
// A: M x Kd row-major (lda), B: Kd x N row-major dense, C: M x N (ldc).
// ACT: 0 = none, 1 = leaky_relu(0.15). Requires Kd%32==0, N%128==0, lda%4==0.

__device__ __forceinline__ uint32_t f2tf32(float x) {
    uint32_t r;
    asm("cvt.rna.tf32.f32 %0, %1;" : "=r"(r) : "f"(x));
    return r;
}

__device__ __forceinline__ void mma_tf32(float c[4], const uint32_t a[4], const uint32_t b[2]) {
    asm volatile(
        "mma.sync.aligned.m16n8k8.row.col.f32.tf32.tf32.f32 "
        "{%0,%1,%2,%3}, {%4,%5,%6,%7}, {%8,%9}, {%0,%1,%2,%3};\n"
        : "+f"(c[0]), "+f"(c[1]), "+f"(c[2]), "+f"(c[3])
        : "r"(a[0]), "r"(a[1]), "r"(a[2]), "r"(a[3]), "r"(b[0]), "r"(b[1]));
}

template <int ACT>
__global__ __launch_bounds__(256)
void gemm_tc(const float* __restrict__ A, const float* __restrict__ B,
             const float* __restrict__ bias, float* __restrict__ C,
             int M, int N, int Kd, int lda, int ldc) {
    __shared__ uint32_t As[32][136];  // [k][m] tf32
    __shared__ uint32_t Bs[32][136];  // [k][n] tf32

    const int t = threadIdx.x;
    const int wid = t >> 5;
    const int lane = t & 31;
    const int wm = wid & 1;    // warp row (2)
    const int wn = wid >> 1;   // warp col (4)
    const int bm = blockIdx.y * 128;
    const int bn = blockIdx.x * 128;
    const int r = lane >> 2;   // group id
    const int c = lane & 3;    // thread in group

    float acc[4][4][4];
#pragma unroll
    for (int i = 0; i < 4; i++)
#pragma unroll
        for (int j = 0; j < 4; j++)
#pragma unroll
            for (int q = 0; q < 4; q++) acc[i][j][q] = 0.f;

    for (int k0 = 0; k0 < Kd; k0 += 32) {
        // load A tile: 128 rows x 32 k
#pragma unroll
        for (int i = 0; i < 4; i++) {
            int e = t + i * 256;
            int row = e >> 3;       // 0..127
            int kq = e & 7;         // k = kq*4
            float4 av = make_float4(0.f, 0.f, 0.f, 0.f);
            int gm = bm + row;
            if (gm < M)
                av = *reinterpret_cast<const float4*>(A + (size_t)gm * lda + k0 + kq * 4);
            As[kq * 4 + 0][row] = f2tf32(av.x);
            As[kq * 4 + 1][row] = f2tf32(av.y);
            As[kq * 4 + 2][row] = f2tf32(av.z);
            As[kq * 4 + 3][row] = f2tf32(av.w);
        }
        // load B tile: 32 k x 128 n
#pragma unroll
        for (int i = 0; i < 4; i++) {
            int e = t + i * 256;
            int kr = e >> 5;        // 0..31
            int n4 = e & 31;        // n = n4*4
            float4 bv = *reinterpret_cast<const float4*>(B + (size_t)(k0 + kr) * N + bn + n4 * 4);
            Bs[kr][n4 * 4 + 0] = f2tf32(bv.x);
            Bs[kr][n4 * 4 + 1] = f2tf32(bv.y);
            Bs[kr][n4 * 4 + 2] = f2tf32(bv.z);
            Bs[kr][n4 * 4 + 3] = f2tf32(bv.w);
        }
        __syncthreads();

#pragma unroll
        for (int ks = 0; ks < 4; ks++) {
            uint32_t afr[4][4];
            uint32_t bfr[4][2];
#pragma unroll
            for (int im = 0; im < 4; im++) {
                int m = wm * 64 + im * 16;
                afr[im][0] = As[ks * 8 + c][m + r];
                afr[im][1] = As[ks * 8 + c][m + r + 8];
                afr[im][2] = As[ks * 8 + c + 4][m + r];
                afr[im][3] = As[ks * 8 + c + 4][m + r + 8];
            }
#pragma unroll
            for (int in = 0; in < 4; in++) {
                int n = wn * 32 + in * 8;
                bfr[in][0] = Bs[ks * 8 + c][n + r];
                bfr[in][1] = Bs[ks * 8 + c + 4][n + r];
            }
#pragma unroll
            for (int im = 0; im < 4; im++)
#pragma unroll
                for (int in = 0; in < 4; in++)
                    mma_tf32(acc[im][in], afr[im], bfr[in]);
        }
        __syncthreads();
    }

    // epilogue
#pragma unroll
    for (int im = 0; im < 4; im++) {
        int gm0 = bm + wm * 64 + im * 16 + r;
#pragma unroll
        for (int in = 0; in < 4; in++) {
            int gn = bn + wn * 32 + in * 8 + c * 2;
            float b0 = bias[gn], b1 = bias[gn + 1];
            float v0 = acc[im][in][0] + b0;
            float v1 = acc[im][in][1] + b1;
            float v2 = acc[im][in][2] + b0;
            float v3 = acc[im][in][3] + b1;
            if (ACT == 1) {
                v0 = v0 > 0.f ? v0 : 0.15f * v0;
                v1 = v1 > 0.f ? v1 : 0.15f * v1;
                v2 = v2 > 0.f ? v2 : 0.15f * v2;
                v3 = v3 > 0.f ? v3 : 0.15f * v3;
            }
            if (gm0 < M)
                *reinterpret_cast<float2*>(C + (size_t)gm0 * ldc + gn) = make_float2(v0, v1);
            if (gm0 + 8 < M)
                *reinterpret_cast<float2*>(C + (size_t)(gm0 + 8) * ldc + gn) = make_float2(v2, v3);
        }
    }
}

// fc4: 256 -> 3, tanh * 0.1, + coord. One warp per vertex.
__global__ void k_fc4(const float* __restrict__ v, const float* __restrict__ w,
                      const float* __restrict__ b, float* __restrict__ out) {
    int gtid = blockIdx.x * blockDim.x + threadIdx.x;
    int vert = gtid >> 5;
    int lane = threadIdx.x & 31;
    if (vert >= NV) return;
    const float* h = g_h3 + (size_t)vert * 256;
    float s0 = 0.f, s1 = 0.f, s2 = 0.f;
#pragma unroll
    for (int i = 0; i < 8; i++) {
        int k = lane + i * 32;
        float x = h[k];
        s0 += x * w[k * 3 + 0];
        s1 += x * w[k * 3 + 1];
        s2 += x * w[k * 3 + 2];
    }
#pragma unroll
    for (int off = 16; off > 0; off >>= 1) {
        s0 += __shfl_down_sync(0xFFFFFFFFu, s0, off);
        s1 += __shfl_down_sync(0xFFFFFFFFu, s1, off);
        s2 += __shfl_down_sync(0xFFFFFFFFu, s2, off);
    }
    if (lane == 0) {
        out[vert * 3 + 0] = v[vert * 3 + 0] + 0.1f * tanhf(s0 + b[0]);
        out[vert * 3 + 1] = v[vert * 3 + 1] + 0.1f * tanhf(s1 + b[1]);
        out[vert * 3 + 2] = v[vert * 3 + 2] + 0.1f * tanhf(s2 + b[2]);
    }
}

// ---------------- launch ----------------------------------------------------
extern "C" void kernel_launch(void* const* d_in, const int* in_sizes, int n_in,
                              void* d_out, int out_size) {
    const float* v      = (const float*)d_in[0];
    const int*   f      = (const int*)d_in[1];
    const float* volume = (const float*)d_in[2];
    const float* fc1_w  = (const float*)d_in[3];
    const float* fc1_b  = (const float*)d_in[4];
    const float* fc2_w  = (const float*)d_in[5];
    const float* fc2_b  = (const float*)d_in[6];
    const float* fc3_w  = (const float*)d_in[7];
    const float* fc3_b  = (const float*)d_in[8];
    const float* fc4_w  = (const float*)d_in[9];
    const float* fc4_b  = (const float*)d_in[10];
    const float* conv_w = (const float*)d_in[11];
    const float* conv_b = (const float*)d_in[12];
    const float* lfc_w  = (const float*)d_in[13];
    const float* lfc_b  = (const float*)d_in[14];
    float* out = (float*)d_out;

    float *p_nrm, *p_vol1, *p_vol2, *p_cubes, *p_xcat, *p_xl0, *p_h2, *p_h3, *p_convT;
    cudaGetSymbolAddress((void**)&p_nrm, g_nrm);
    cudaGetSymbolAddress((void**)&p_vol1, g_vol1);
    cudaGetSymbolAddress((void**)&p_vol2, g_vol2);
    cudaGetSymbolAddress((void**)&p_cubes, g_cubes);
    cudaGetSymbolAddress((void**)&p_xcat, g_xcat);
    cudaGetSymbolAddress((void**)&p_xl0, g_xl0);
    cudaGetSymbolAddress((void**)&p_h2, g_h2);
    cudaGetSymbolAddress((void**)&p_h3, g_h3);
    cudaGetSymbolAddress((void**)&p_convT, g_convT);

    // 1. normals: zero + scatter
    k_zero<<<(NV * 3 + 255) / 256, 256>>>(p_nrm, NV * 3);
    k_face_normals<<<(NFACE + 255) / 256, 256>>>(v, f);

    // 2. volume pyramid
    k_down<<<(L1 * L1 * L1 + 255) / 256, 256>>>(volume, p_vol1, L1);
    k_down<<<(L2DIM * L2DIM * L2DIM + 255) / 256, 256>>>(p_vol1, p_vol2, L2DIM);

    // 3. conv weight transpose (375x128, padded to 384)
    k_convT<<<(KC * 128 + 255) / 256, 256>>>(conv_w);

    // 4. fc1 (+normal normalize) -> xcat[:, 0:128]
    k_fc1<<<NV, 128>>>(v, fc1_w, fc1_b);

    // 5. cube gather -> g_cubes [NV x 384]
    k_gather<<<NV, 128>>>(v, volume);

    const int MB = (NV + 127) / 128;

    // 6. conv einsum: cubes[NV,384] x convT[384,128] + conv_b -> xl0
    gemm_tc<0><<<dim3(128 / 128, MB), 256>>>(p_cubes, p_convT, conv_b, p_xl0,
                                             NV, 128, KC, KC, 128);

    // 7. lfc: xl0[NV,128] x lfc_w[128,128] + lfc_b -> xcat[:, 128:256]
    gemm_tc<0><<<dim3(128 / 128, MB), 256>>>(p_xl0, lfc_w, lfc_b, p_xcat + 128,
                                             NV, 128, 128, 128, 256);

    // 8. fc2: xcat[NV,256] x fc2_w[256,512] + b, leaky -> h2
    gemm_tc<1><<<dim3(512 / 128, MB), 256>>>(p_xcat, fc2_w, fc2_b, p_h2,
                                             NV, 512, 256, 256, 512);

    // 9. fc3: h2[NV,512] x fc3_w[512,256] + b, leaky -> h3
    gemm_tc<1><<<dim3(256 / 128, MB), 256>>>(p_h2, fc3_w, fc3_b, p_h3,
                                             NV, 256, 512, 512, 256);

    // 10. fc4 + tanh*0.1 + coord
    k_fc4<<<(NV * 32 + 255) / 256, 256>>>(v, fc4_w, fc4_b, out);
}

// round 5
// speedup vs baseline: 2.5641x; 1.6894x over previous
#include <cuda_runtime.h>
#include <cuda_bf16.h>
#include <cstdint>
#include <math.h>

#define NV 150000
#define NFACE 300000
#define L0 192
#define L1 96
#define L2DIM 48
#define KC 384            // padded conv K (375 -> 384)

typedef __nv_bfloat16 bf16;

// ---------------- scratch (device globals; no allocation allowed) ----------
__device__ float g_nrm[NV * 3];
__device__ float g_vol1[L1 * L1 * L1];
__device__ float g_vol2[L2DIM * L2DIM * L2DIM];
__device__ bf16  g_cubes[(size_t)NV * KC];
__device__ bf16  g_xcat[(size_t)NV * 256];      // fc1 out | lfc out
__device__ bf16  g_xl0[(size_t)NV * 128];
__device__ bf16  g_h2[(size_t)NV * 512];
__device__ bf16  g_h3[(size_t)NV * 256];
// pre-transposed bf16 weights, layout [N][K]
__device__ bf16  g_wconv[128 * KC];
__device__ bf16  g_wlfc[128 * 128];
__device__ bf16  g_w2[512 * 256];
__device__ bf16  g_w3[256 * 512];

// ---------------- small kernels --------------------------------------------
__global__ void k_zero(float* p, int n) {
    int i = blockIdx.x * blockDim.x + threadIdx.x;
    if (i < n) p[i] = 0.f;
}

__global__ void k_face_normals(const float* __restrict__ v, const int* __restrict__ f) {
    int i = blockIdx.x * blockDim.x + threadIdx.x;
    if (i >= NFACE) return;
    int i0 = f[i * 3 + 0], i1 = f[i * 3 + 1], i2 = f[i * 3 + 2];
    float p0x = v[i0 * 3], p0y = v[i0 * 3 + 1], p0z = v[i0 * 3 + 2];
    float p1x = v[i1 * 3], p1y = v[i1 * 3 + 1], p1z = v[i1 * 3 + 2];
    float p2x = v[i2 * 3], p2y = v[i2 * 3 + 1], p2z = v[i2 * 3 + 2];
    float ax = p1x - p0x, ay = p1y - p0y, az = p1z - p0z;
    float bx = p2x - p0x, by = p2y - p0y, bz = p2z - p0z;
    float cx = ay * bz - az * by;
    float cy = az * bx - ax * bz;
    float cz = ax * by - ay * bx;
    atomicAdd(&g_nrm[i0 * 3 + 0], cx); atomicAdd(&g_nrm[i0 * 3 + 1], cy); atomicAdd(&g_nrm[i0 * 3 + 2], cz);
    atomicAdd(&g_nrm[i1 * 3 + 0], cx); atomicAdd(&g_nrm[i1 * 3 + 1], cy); atomicAdd(&g_nrm[i1 * 3 + 2], cz);
    atomicAdd(&g_nrm[i2 * 3 + 0], cx); atomicAdd(&g_nrm[i2 * 3 + 1], cy); atomicAdd(&g_nrm[i2 * 3 + 2], cz);
}

__global__ void k_down(const float* __restrict__ src, float* __restrict__ dst, int s) {
    int i = blockIdx.x * blockDim.x + threadIdx.x;
    int tot = s * s * s;
    if (i >= tot) return;
    int c = i % s, b = (i / s) % s, a = i / (s * s);
    int S = 2 * s;
    float sum = 0.f;
#pragma unroll
    for (int da = 0; da < 2; da++)
#pragma unroll
        for (int db = 0; db < 2; db++)
#pragma unroll
            for (int dc = 0; dc < 2; dc++)
                sum += src[((size_t)(2 * a + da) * S + (2 * b + db)) * S + (2 * c + dc)];
    dst[i] = sum * 0.125f;
}

// conv_w [128][375] fp32 -> g_wconv [128][384] bf16 (pad zeros)
__global__ void k_prep_convw(const float* __restrict__ w) {
    int i = blockIdx.x * blockDim.x + threadIdx.x;
    if (i >= 128 * KC) return;
    int o = i / KC, c = i % KC;
    g_wconv[i] = __float2bfloat16(c < 375 ? w[o * 375 + c] : 0.f);
}

// transpose fp32 [K][N] -> bf16 [N][K]
__global__ void k_transpose(const float* __restrict__ in, bf16* __restrict__ out, int K, int N) {
    int i = blockIdx.x * blockDim.x + threadIdx.x;
    if (i >= K * N) return;
    int n = i / K, k = i % K;
    out[i] = __float2bfloat16(in[(size_t)k * N + n]);
}

// per-vertex: normalize normal, fc1 (6->128) + leaky, write bf16 xcat[:,0:128]
__global__ void k_fc1(const float* __restrict__ v, const float* __restrict__ w,
                      const float* __restrict__ b) {
    int vid = blockIdx.x;
    int o = threadIdx.x;  // 128
    float in0 = v[vid * 3 + 0], in1 = v[vid * 3 + 1], in2 = v[vid * 3 + 2];
    float nx = g_nrm[vid * 3 + 0], ny = g_nrm[vid * 3 + 1], nz = g_nrm[vid * 3 + 2];
    float nn = fmaxf(sqrtf(nx * nx + ny * ny + nz * nz), 1e-12f);
    float in3 = nx / nn, in4 = ny / nn, in5 = nz / nn;
    float acc = b[o];
    acc += in0 * w[0 * 128 + o];
    acc += in1 * w[1 * 128 + o];
    acc += in2 * w[2 * 128 + o];
    acc += in3 * w[3 * 128 + o];
    acc += in4 * w[4 * 128 + o];
    acc += in5 * w[5 * 128 + o];
    float r = acc > 0.f ? acc : 0.15f * acc;
    g_xcat[(size_t)vid * 256 + o] = __float2bfloat16(r);
}

// gather 3-scale 5x5x5 cubes -> bf16 g_cubes[v][384]
__global__ void k_gather(const float* __restrict__ v, const float* __restrict__ vol0) {
    int vid = blockIdx.x;
    float vx = v[vid * 3 + 0], vy = v[vid * 3 + 1], vz = v[vid * 3 + 2];
    for (int c = threadIdx.x; c < KC; c += blockDim.x) {
        float val = 0.f;
        if (c < 375) {
            int n = c / 125, r = c % 125;
            int di = r / 25, dj = (r / 5) % 5, dk = r % 5;
            const float* vol;
            int dim;
            float scale;
            if (n == 0)      { vol = vol0;   dim = L0;    scale = 96.f; }
            else if (n == 1) { vol = g_vol1; dim = L1;    scale = 48.f; }
            else             { vol = g_vol2; dim = L2DIM; scale = 24.f; }
            int hi = dim - 3;
            int i0 = min(max((int)rintf((vx + 1.f) * scale), 2), hi) + di - 2;
            int i1 = min(max((int)rintf((vy + 1.f) * scale), 2), hi) + dj - 2;
            int i2 = min(max((int)rintf((vz + 1.f) * scale), 2), hi) + dk - 2;
            val = vol[((size_t)i0 * dim + i1) * dim + i2];
        }
        g_cubes[(size_t)vid * KC + c] = __float2bfloat16(val);
    }
}

// ---------------- bf16 m16n8k16 tensor-core GEMM ---------------------------
// C[M x ldc](bf16) = act(A[M x K](bf16) @ B^T + bias), B given as [Ntot][K] bf16.
// Block tile 128x128, warp tile 64x32, BK=64 (32 k-pairs), 256 threads.
// smem layout: [kpair][m or n] of uint32 (bf16x2 along k).

__device__ __forceinline__ void mma_bf16(float c[4], const uint32_t a[4], const uint32_t b[2]) {
    asm volatile(
        "mma.sync.aligned.m16n8k16.row.col.f32.bf16.bf16.f32 "
        "{%0,%1,%2,%3}, {%4,%5,%6,%7}, {%8,%9}, {%0,%1,%2,%3};\n"
        : "+f"(c[0]), "+f"(c[1]), "+f"(c[2]), "+f"(c[3])
        : "r"(a[0]), "r"(a[1]), "r"(a[2]), "r"(a[3]), "r"(b[0]), "r"(b[1]));
}

template <int ACT>
__global__ __launch_bounds__(256)
void gemm_bf(const bf16* __restrict__ A, const bf16* __restrict__ B,
             const float* __restrict__ bias, bf16* __restrict__ C,
             int M, int N, int Kd, int ldc) {
    __shared__ uint32_t As[32][136];  // [kpair][m]
    __shared__ uint32_t Bs[32][136];  // [kpair][n]

    const int t = threadIdx.x;
    const int wid = t >> 5;
    const int lane = t & 31;
    const int wm = wid & 1;    // warp row (2)
    const int wn = wid >> 1;   // warp col (4)
    const int bm = blockIdx.y * 128;
    const int bn = blockIdx.x * 128;
    const int r = lane >> 2;   // group id (0..7)
    const int c = lane & 3;    // thread in group (0..3)

    float acc[4][4][4];
#pragma unroll
    for (int i = 0; i < 4; i++)
#pragma unroll
        for (int j = 0; j < 4; j++)
#pragma unroll
            for (int q = 0; q < 4; q++) acc[i][j][q] = 0.f;

    for (int k0 = 0; k0 < Kd; k0 += 64) {
        // A tile: 128 rows x 64 k (bf16). 1024 uint4 loads / 256 thr = 4 each.
#pragma unroll
        for (int i = 0; i < 4; i++) {
            int e = t + i * 256;
            int row = e >> 3;       // 0..127
            int seg = e & 7;        // kpair base = seg*4
            uint4 av = make_uint4(0u, 0u, 0u, 0u);
            int gm = bm + row;
            if (gm < M)
                av = *reinterpret_cast<const uint4*>(A + (size_t)gm * Kd + k0 + seg * 8);
            As[seg * 4 + 0][row] = av.x;
            As[seg * 4 + 1][row] = av.y;
            As[seg * 4 + 2][row] = av.z;
            As[seg * 4 + 3][row] = av.w;
        }
        // B tile: 128 n-rows x 64 k
#pragma unroll
        for (int i = 0; i < 4; i++) {
            int e = t + i * 256;
            int row = e >> 3;
            int seg = e & 7;
            uint4 bv = *reinterpret_cast<const uint4*>(B + (size_t)(bn + row) * Kd + k0 + seg * 8);
            Bs[seg * 4 + 0][row] = bv.x;
            Bs[seg * 4 + 1][row] = bv.y;
            Bs[seg * 4 + 2][row] = bv.z;
            Bs[seg * 4 + 3][row] = bv.w;
        }
        __syncthreads();

#pragma unroll
        for (int ks = 0; ks < 4; ks++) {   // 4 x k16 steps
            uint32_t afr[4][4];
            uint32_t bfr[4][2];
#pragma unroll
            for (int im = 0; im < 4; im++) {
                int m = wm * 64 + im * 16;
                afr[im][0] = As[ks * 8 + c][m + r];
                afr[im][1] = As[ks * 8 + c][m + r + 8];
                afr[im][2] = As[ks * 8 + c + 4][m + r];
                afr[im][3] = As[ks * 8 + c + 4][m + r + 8];
            }
#pragma unroll
            for (int in = 0; in < 4; in++) {
                int n = wn * 32 + in * 8;
                bfr[in][0] = Bs[ks * 8 + c][n + r];
                bfr[in][1] = Bs[ks * 8 + c + 4][n + r];
            }
#pragma unroll
            for (int im = 0; im < 4; im++)
#pragma unroll
                for (int in = 0; in < 4; in++)
                    mma_bf16(acc[im][in], afr[im], bfr[in]);
        }
        __syncthreads();
    }

    // epilogue: bf16 stores
#pragma unroll
    for (int im = 0; im < 4; im++) {
        int gm0 = bm + wm * 64 + im * 16 + r;
#pragma unroll
        for (int in = 0; in < 4; in++) {
            int gn = bn + wn * 32 + in * 8 + c * 2;
            float b0 = bias[gn], b1 = bias[gn + 1];
            float v0 = acc[im][in][0] + b0;
            float v1 = acc[im][in][1] + b1;
            float v2 = acc[im][in][2] + b0;
            float v3 = acc[im][in][3] + b1;
            if (ACT == 1) {
                v0 = v0 > 0.f ? v0 : 0.15f * v0;
                v1 = v1 > 0.f ? v1 : 0.15f * v1;
                v2 = v2 > 0.f ? v2 : 0.15f * v2;
                v3 = v3 > 0.f ? v3 : 0.15f * v3;
            }
            if (gm0 < M) {
                __nv_bfloat162 p = __floats2bfloat162_rn(v0, v1);
                *reinterpret_cast<uint32_t*>(C + (size_t)gm0 * ldc + gn) =
                    *reinterpret_cast<uint32_t*>(&p);
            }
            if (gm0 + 8 < M) {
                __nv_bfloat162 p = __floats2bfloat162_rn(v2, v3);
                *reinterpret_cast<uint32_t*>(C + (size_t)(gm0 + 8) * ldc + gn) =
                    *reinterpret_cast<uint32_t*>(&p);
            }
        }
    }
}

// fc4: 256 -> 3 from bf16 h3, tanh * 0.1, + coord. One warp per vertex.
__global__ void k_fc4(const float* __restrict__ v, const float* __restrict__ w,
                      const float* __restrict__ b, float* __restrict__ out) {
    int gtid = blockIdx.x * blockDim.x + threadIdx.x;
    int vert = gtid >> 5;
    int lane = threadIdx.x & 31;
    if (vert >= NV) return;
    const bf16* h = g_h3 + (size_t)vert * 256;
    float s0 = 0.f, s1 = 0.f, s2 = 0.f;
#pragma unroll
    for (int i = 0; i < 8; i++) {
        int k = lane + i * 32;
        float x = __bfloat162float(h[k]);
        s0 += x * w[k * 3 + 0];
        s1 += x * w[k * 3 + 1];
        s2 += x * w[k * 3 + 2];
    }
#pragma unroll
    for (int off = 16; off > 0; off >>= 1) {
        s0 += __shfl_down_sync(0xFFFFFFFFu, s0, off);
        s1 += __shfl_down_sync(0xFFFFFFFFu, s1, off);
        s2 += __shfl_down_sync(0xFFFFFFFFu, s2, off);
    }
    if (lane == 0) {
        out[vert * 3 + 0] = v[vert * 3 + 0] + 0.1f * tanhf(s0 + b[0]);
        out[vert * 3 + 1] = v[vert * 3 + 1] + 0.1f * tanhf(s1 + b[1]);
        out[vert * 3 + 2] = v[vert * 3 + 2] + 0.1f * tanhf(s2 + b[2]);
    }
}

// ---------------- launch ----------------------------------------------------
extern "C" void kernel_launch(void* const* d_in, const int* in_sizes, int n_in,
                              void* d_out, int out_size) {
    const float* v      = (const float*)d_in[0];
    const int*   f      = (const int*)d_in[1];
    const float* volume = (const float*)d_in[2];
    const float* fc1_w  = (const float*)d_in[3];
    const float* fc1_b  = (const float*)d_in[4];
    const float* fc2_w  = (const float*)d_in[5];
    const float* fc2_b  = (const float*)d_in[6];
    const float* fc3_w  = (const float*)d_in[7];
    const float* fc3_b  = (const float*)d_in[8];
    const float* fc4_w  = (const float*)d_in[9];
    const float* fc4_b  = (const float*)d_in[10];
    const float* conv_w = (const float*)d_in[11];
    const float* conv_b = (const float*)d_in[12];
    const float* lfc_w  = (const float*)d_in[13];
    const float* lfc_b  = (const float*)d_in[14];
    float* out = (float*)d_out;

    float *p_nrm, *p_vol1, *p_vol2;
    bf16 *p_cubes, *p_xcat, *p_xl0, *p_h2, *p_h3, *p_wconv, *p_wlfc, *p_w2, *p_w3;
    cudaGetSymbolAddress((void**)&p_nrm, g_nrm);
    cudaGetSymbolAddress((void**)&p_vol1, g_vol1);
    cudaGetSymbolAddress((void**)&p_vol2, g_vol2);
    cudaGetSymbolAddress((void**)&p_cubes, g_cubes);
    cudaGetSymbolAddress((void**)&p_xcat, g_xcat);
    cudaGetSymbolAddress((void**)&p_xl0, g_xl0);
    cudaGetSymbolAddress((void**)&p_h2, g_h2);
    cudaGetSymbolAddress((void**)&p_h3, g_h3);
    cudaGetSymbolAddress((void**)&p_wconv, g_wconv);
    cudaGetSymbolAddress((void**)&p_wlfc, g_wlfc);
    cudaGetSymbolAddress((void**)&p_w2, g_w2);
    cudaGetSymbolAddress((void**)&p_w3, g_w3);

    // 1. normals
    k_zero<<<(NV * 3 + 255) / 256, 256>>>(p_nrm, NV * 3);
    k_face_normals<<<(NFACE + 255) / 256, 256>>>(v, f);

    // 2. volume pyramid
    k_down<<<(L1 * L1 * L1 + 255) / 256, 256>>>(volume, p_vol1, L1);
    k_down<<<(L2DIM * L2DIM * L2DIM + 255) / 256, 256>>>(p_vol1, p_vol2, L2DIM);

    // 3. weight prep (bf16, [N][K])
    k_prep_convw<<<(128 * KC + 255) / 256, 256>>>(conv_w);
    k_transpose<<<(128 * 128 + 255) / 256, 256>>>(lfc_w, p_wlfc, 128, 128);
    k_transpose<<<(256 * 512 + 255) / 256, 256>>>(fc2_w, p_w2, 256, 512);
    k_transpose<<<(512 * 256 + 255) / 256, 256>>>(fc3_w, p_w3, 512, 256);

    // 4. fc1 -> xcat[:, 0:128]
    k_fc1<<<NV, 128>>>(v, fc1_w, fc1_b);

    // 5. cube gather -> g_cubes [NV x 384] bf16
    k_gather<<<NV, 128>>>(v, volume);

    const int MB = (NV + 127) / 128;

    // 6. conv: cubes[NV,384] @ wconv^T -> xl0 [NV,128]
    gemm_bf<0><<<dim3(1, MB), 256>>>(p_cubes, p_wconv, conv_b, p_xl0, NV, 128, KC, 128);
    // 7. lfc: xl0 @ wlfc^T -> xcat[:, 128:256]
    gemm_bf<0><<<dim3(1, MB), 256>>>(p_xl0, p_wlfc, lfc_b, p_xcat + 128, NV, 128, 128, 256);
    // 8. fc2: xcat[NV,256] @ w2^T + b, leaky -> h2 [NV,512]
    gemm_bf<1><<<dim3(4, MB), 256>>>(p_xcat, p_w2, fc2_b, p_h2, NV, 512, 256, 512);
    // 9. fc3: h2[NV,512] @ w3^T + b, leaky -> h3 [NV,256]
    gemm_bf<1><<<dim3(2, MB), 256>>>(p_h2, p_w3, fc3_b, p_h3, NV, 256, 512, 256);

    // 10. fc4 + tanh*0.1 + coord
    k_fc4<<<(NV * 32 + 255) / 256, 256>>>(v, fc4_w, fc4_b, out);
}

// round 6
// speedup vs baseline: 3.7411x; 1.4590x over previous
#include <cuda_runtime.h>
#include <cuda_bf16.h>
#include <cstdint>
#include <math.h>

#define NV 150000
#define NFACE 300000
#define L0 192
#define L1 96
#define L2DIM 48
#define KC 384            // padded conv K (375 -> 384)

typedef __nv_bfloat16 bf16;

// ---------------- scratch (device globals; no allocation allowed) ----------
__device__ float g_nrm[NV * 3];
__device__ float g_vol1[L1 * L1 * L1];
__device__ float g_vol2[L2DIM * L2DIM * L2DIM];
__device__ bf16  g_cubes[(size_t)NV * KC];
__device__ bf16  g_xcat[(size_t)NV * 256];      // fc1 out | lfc out
__device__ bf16  g_xl0[(size_t)NV * 128];
__device__ bf16  g_h2[(size_t)NV * 512];
__device__ bf16  g_h3[(size_t)NV * 256];
// pre-transposed bf16 weights, layout [N][K]
__device__ bf16  g_wconv[128 * KC];
__device__ bf16  g_wlfc[128 * 128];
__device__ bf16  g_w2[512 * 256];
__device__ bf16  g_w3[256 * 512];

// ---------------- small kernels --------------------------------------------
__global__ void k_zero(float* p, int n) {
    int i = blockIdx.x * blockDim.x + threadIdx.x;
    if (i < n) p[i] = 0.f;
}

__global__ void k_face_normals(const float* __restrict__ v, const int* __restrict__ f) {
    int i = blockIdx.x * blockDim.x + threadIdx.x;
    if (i >= NFACE) return;
    int i0 = f[i * 3 + 0], i1 = f[i * 3 + 1], i2 = f[i * 3 + 2];
    float p0x = v[i0 * 3], p0y = v[i0 * 3 + 1], p0z = v[i0 * 3 + 2];
    float p1x = v[i1 * 3], p1y = v[i1 * 3 + 1], p1z = v[i1 * 3 + 2];
    float p2x = v[i2 * 3], p2y = v[i2 * 3 + 1], p2z = v[i2 * 3 + 2];
    float ax = p1x - p0x, ay = p1y - p0y, az = p1z - p0z;
    float bx = p2x - p0x, by = p2y - p0y, bz = p2z - p0z;
    float cx = ay * bz - az * by;
    float cy = az * bx - ax * bz;
    float cz = ax * by - ay * bx;
    atomicAdd(&g_nrm[i0 * 3 + 0], cx); atomicAdd(&g_nrm[i0 * 3 + 1], cy); atomicAdd(&g_nrm[i0 * 3 + 2], cz);
    atomicAdd(&g_nrm[i1 * 3 + 0], cx); atomicAdd(&g_nrm[i1 * 3 + 1], cy); atomicAdd(&g_nrm[i1 * 3 + 2], cz);
    atomicAdd(&g_nrm[i2 * 3 + 0], cx); atomicAdd(&g_nrm[i2 * 3 + 1], cy); atomicAdd(&g_nrm[i2 * 3 + 2], cz);
}

__global__ void k_down(const float* __restrict__ src, float* __restrict__ dst, int s) {
    int i = blockIdx.x * blockDim.x + threadIdx.x;
    int tot = s * s * s;
    if (i >= tot) return;
    int c = i % s, b = (i / s) % s, a = i / (s * s);
    int S = 2 * s;
    float sum = 0.f;
#pragma unroll
    for (int da = 0; da < 2; da++)
#pragma unroll
        for (int db = 0; db < 2; db++)
#pragma unroll
            for (int dc = 0; dc < 2; dc++)
                sum += src[((size_t)(2 * a + da) * S + (2 * b + db)) * S + (2 * c + dc)];
    dst[i] = sum * 0.125f;
}

// conv_w [128][375] fp32 -> g_wconv [128][384] bf16 (pad zeros)
__global__ void k_prep_convw(const float* __restrict__ w) {
    int i = blockIdx.x * blockDim.x + threadIdx.x;
    if (i >= 128 * KC) return;
    int o = i / KC, c = i % KC;
    g_wconv[i] = __float2bfloat16(c < 375 ? w[o * 375 + c] : 0.f);
}

// transpose fp32 [K][N] -> bf16 [N][K]
__global__ void k_transpose(const float* __restrict__ in, bf16* __restrict__ out, int K, int N) {
    int i = blockIdx.x * blockDim.x + threadIdx.x;
    if (i >= K * N) return;
    int n = i / K, k = i % K;
    out[i] = __float2bfloat16(in[(size_t)k * N + n]);
}

// per-vertex: normalize normal, fc1 (6->128) + leaky, write bf16 xcat[:,0:128]
__global__ void k_fc1(const float* __restrict__ v, const float* __restrict__ w,
                      const float* __restrict__ b) {
    int vid = blockIdx.x;
    int o = threadIdx.x;  // 128
    float in0 = v[vid * 3 + 0], in1 = v[vid * 3 + 1], in2 = v[vid * 3 + 2];
    float nx = g_nrm[vid * 3 + 0], ny = g_nrm[vid * 3 + 1], nz = g_nrm[vid * 3 + 2];
    float nn = fmaxf(sqrtf(nx * nx + ny * ny + nz * nz), 1e-12f);
    float in3 = nx / nn, in4 = ny / nn, in5 = nz / nn;
    float acc = b[o];
    acc += in0 * w[0 * 128 + o];
    acc += in1 * w[1 * 128 + o];
    acc += in2 * w[2 * 128 + o];
    acc += in3 * w[3 * 128 + o];
    acc += in4 * w[4 * 128 + o];
    acc += in5 * w[5 * 128 + o];
    float r = acc > 0.f ? acc : 0.15f * acc;
    g_xcat[(size_t)vid * 256 + o] = __float2bfloat16(r);
}

// gather 3-scale 5x5x5 cubes -> bf16 g_cubes[v][384]
__global__ void k_gather(const float* __restrict__ v, const float* __restrict__ vol0) {
    int vid = blockIdx.x;
    float vx = v[vid * 3 + 0], vy = v[vid * 3 + 1], vz = v[vid * 3 + 2];
    for (int c = threadIdx.x; c < KC; c += blockDim.x) {
        float val = 0.f;
        if (c < 375) {
            int n = c / 125, r = c % 125;
            int di = r / 25, dj = (r / 5) % 5, dk = r % 5;
            const float* vol;
            int dim;
            float scale;
            if (n == 0)      { vol = vol0;   dim = L0;    scale = 96.f; }
            else if (n == 1) { vol = g_vol1; dim = L1;    scale = 48.f; }
            else             { vol = g_vol2; dim = L2DIM; scale = 24.f; }
            int hi = dim - 3;
            int i0 = min(max((int)rintf((vx + 1.f) * scale), 2), hi) + di - 2;
            int i1 = min(max((int)rintf((vy + 1.f) * scale), 2), hi) + dj - 2;
            int i2 = min(max((int)rintf((vz + 1.f) * scale), 2), hi) + dk - 2;
            val = vol[((size_t)i0 * dim + i1) * dim + i2];
        }
        g_cubes[(size_t)vid * KC + c] = __float2bfloat16(val);
    }
}

// ---------------- bf16 m16n8k16 GEMM, ldmatrix + cp.async ------------------
// C[M x ldc](bf16) = act(A[M x K](bf16) @ B^T + bias), B as [Ntot][K] bf16.
// Block tile 128x128, warp tile 64x32, BK=64, 256 thr, 2-stage cp.async.
// smem tile layout: row-major [row][64 bf16] with chunk swizzle: 16B chunk c
// of row r stored at chunk (c ^ (r&7)).

__device__ __forceinline__ uint32_t smem_u32(const void* p) {
    uint32_t a;
    asm("{ .reg .u64 t; cvta.to.shared.u64 t, %1; cvt.u32.u64 %0, t; }" : "=r"(a) : "l"(p));
    return a;
}

__device__ __forceinline__ void mma_bf16(float c[4], const uint32_t a[4], const uint32_t b[2]) {
    asm volatile(
        "mma.sync.aligned.m16n8k16.row.col.f32.bf16.bf16.f32 "
        "{%0,%1,%2,%3}, {%4,%5,%6,%7}, {%8,%9}, {%0,%1,%2,%3};\n"
        : "+f"(c[0]), "+f"(c[1]), "+f"(c[2]), "+f"(c[3])
        : "r"(a[0]), "r"(a[1]), "r"(a[2]), "r"(a[3]), "r"(b[0]), "r"(b[1]));
}

__device__ __forceinline__ void ldsm_x4(uint32_t r[4], uint32_t addr) {
    asm volatile("ldmatrix.sync.aligned.m8n8.x4.shared.b16 {%0,%1,%2,%3}, [%4];"
                 : "=r"(r[0]), "=r"(r[1]), "=r"(r[2]), "=r"(r[3]) : "r"(addr));
}

#define GEMM_SMEM (4 * 16384)

template <int ACT>
__global__ __launch_bounds__(256)
void gemm_bf(const bf16* __restrict__ A, const bf16* __restrict__ B,
             const float* __restrict__ bias, bf16* __restrict__ C,
             int M, int N, int Kd, int ldc) {
    extern __shared__ char sm[];
    const int t = threadIdx.x;
    const int wid = t >> 5;
    const int lane = t & 31;
    const int wm = wid & 1;
    const int wn = wid >> 1;
    const int bm = blockIdx.y * 128;
    const int bn = blockIdx.x * 128;
    const uint32_t sbase = smem_u32(sm);

    float acc[4][4][4];
#pragma unroll
    for (int i = 0; i < 4; i++)
#pragma unroll
        for (int j = 0; j < 4; j++)
#pragma unroll
            for (int q = 0; q < 4; q++) acc[i][j][q] = 0.f;

    const int nk = Kd >> 6;

    // cp.async fill of one stage (A tile + B tile), 4+4 chunks per thread
    auto issue = [&](int kt, int buf) {
        const int k0 = kt * 64;
#pragma unroll
        for (int i = 0; i < 4; i++) {
            int e = t + i * 256;
            int m = e >> 3, kc = e & 7;
            int gm = bm + m;
            int sz = (gm < M) ? 16 : 0;
            if (gm >= M) gm = M - 1;
            uint32_t dst = sbase + (uint32_t)buf * 16384u + (uint32_t)m * 128u
                         + (uint32_t)((kc ^ (m & 7)) << 4);
            const void* src = A + (size_t)gm * Kd + k0 + kc * 8;
            asm volatile("cp.async.cg.shared.global [%0], [%1], 16, %2;"
                         :: "r"(dst), "l"(src), "r"(sz));
        }
#pragma unroll
        for (int i = 0; i < 4; i++) {
            int e = t + i * 256;
            int n = e >> 3, kc = e & 7;
            uint32_t dst = sbase + 32768u + (uint32_t)buf * 16384u + (uint32_t)n * 128u
                         + (uint32_t)((kc ^ (n & 7)) << 4);
            const void* src = B + (size_t)(bn + n) * Kd + k0 + kc * 8;
            asm volatile("cp.async.cg.shared.global [%0], [%1], 16;"
                         :: "r"(dst), "l"(src));
        }
        asm volatile("cp.async.commit_group;");
    };

    issue(0, 0);

    const int quad = lane >> 3;
    const int lrow = lane & 7;

    for (int kt = 0; kt < nk; kt++) {
        const int buf = kt & 1;
        if (kt + 1 < nk) {
            issue(kt + 1, buf ^ 1);
            asm volatile("cp.async.wait_group 1;");
        } else {
            asm volatile("cp.async.wait_group 0;");
        }
        __syncthreads();

        const uint32_t abase = sbase + (uint32_t)buf * 16384u;
        const uint32_t bbase = sbase + 32768u + (uint32_t)buf * 16384u;

#pragma unroll
        for (int ks = 0; ks < 4; ks++) {
            const int kc0 = ks * 2 + (quad >> 1);
            uint32_t afr[4][4];
            uint32_t bfr[2][4];
#pragma unroll
            for (int im = 0; im < 4; im++) {
                int row = wm * 64 + im * 16 + (quad & 1) * 8 + lrow;
                uint32_t addr = abase + (uint32_t)row * 128u
                              + (uint32_t)((kc0 ^ (row & 7)) << 4);
                ldsm_x4(afr[im], addr);
            }
#pragma unroll
            for (int ib = 0; ib < 2; ib++) {
                int n = wn * 32 + ib * 16 + (quad & 1) * 8 + lrow;
                uint32_t addr = bbase + (uint32_t)n * 128u
                              + (uint32_t)((kc0 ^ (n & 7)) << 4);
                ldsm_x4(bfr[ib], addr);
            }
#pragma unroll
            for (int im = 0; im < 4; im++)
#pragma unroll
                for (int in = 0; in < 4; in++) {
                    uint32_t bb[2] = { bfr[in >> 1][in & 1], bfr[in >> 1][2 + (in & 1)] };
                    mma_bf16(acc[im][in], afr[im], bb);
                }
        }
        __syncthreads();
    }

    // epilogue: bf16 stores
    const int r = lane >> 2;
    const int c = lane & 3;
#pragma unroll
    for (int im = 0; im < 4; im++) {
        int gm0 = bm + wm * 64 + im * 16 + r;
#pragma unroll
        for (int in = 0; in < 4; in++) {
            int gn = bn + wn * 32 + in * 8 + c * 2;
            float b0 = bias[gn], b1 = bias[gn + 1];
            float v0 = acc[im][in][0] + b0;
            float v1 = acc[im][in][1] + b1;
            float v2 = acc[im][in][2] + b0;
            float v3 = acc[im][in][3] + b1;
            if (ACT == 1) {
                v0 = v0 > 0.f ? v0 : 0.15f * v0;
                v1 = v1 > 0.f ? v1 : 0.15f * v1;
                v2 = v2 > 0.f ? v2 : 0.15f * v2;
                v3 = v3 > 0.f ? v3 : 0.15f * v3;
            }
            if (gm0 < M) {
                __nv_bfloat162 p = __floats2bfloat162_rn(v0, v1);
                *reinterpret_cast<uint32_t*>(C + (size_t)gm0 * ldc + gn) =
                    *reinterpret_cast<uint32_t*>(&p);
            }
            if (gm0 + 8 < M) {
                __nv_bfloat162 p = __floats2bfloat162_rn(v2, v3);
                *reinterpret_cast<uint32_t*>(C + (size_t)(gm0 + 8) * ldc + gn) =
                    *reinterpret_cast<uint32_t*>(&p);
            }
        }
    }
}

// fc4: 256 -> 3 from bf16 h3, tanh * 0.1, + coord. One warp per vertex.
__global__ void k_fc4(const float* __restrict__ v, const float* __restrict__ w,
                      const float* __restrict__ b, float* __restrict__ out) {
    int gtid = blockIdx.x * blockDim.x + threadIdx.x;
    int vert = gtid >> 5;
    int lane = threadIdx.x & 31;
    if (vert >= NV) return;
    const bf16* h = g_h3 + (size_t)vert * 256;
    float s0 = 0.f, s1 = 0.f, s2 = 0.f;
#pragma unroll
    for (int i = 0; i < 8; i++) {
        int k = lane + i * 32;
        float x = __bfloat162float(h[k]);
        s0 += x * w[k * 3 + 0];
        s1 += x * w[k * 3 + 1];
        s2 += x * w[k * 3 + 2];
    }
#pragma unroll
    for (int off = 16; off > 0; off >>= 1) {
        s0 += __shfl_down_sync(0xFFFFFFFFu, s0, off);
        s1 += __shfl_down_sync(0xFFFFFFFFu, s1, off);
        s2 += __shfl_down_sync(0xFFFFFFFFu, s2, off);
    }
    if (lane == 0) {
        out[vert * 3 + 0] = v[vert * 3 + 0] + 0.1f * tanhf(s0 + b[0]);
        out[vert * 3 + 1] = v[vert * 3 + 1] + 0.1f * tanhf(s1 + b[1]);
        out[vert * 3 + 2] = v[vert * 3 + 2] + 0.1f * tanhf(s2 + b[2]);
    }
}

// ---------------- launch ----------------------------------------------------
extern "C" void kernel_launch(void* const* d_in, const int* in_sizes, int n_in,
                              void* d_out, int out_size) {
    const float* v      = (const float*)d_in[0];
    const int*   f      = (const int*)d_in[1];
    const float* volume = (const float*)d_in[2];
    const float* fc1_w  = (const float*)d_in[3];
    const float* fc1_b  = (const float*)d_in[4];
    const float* fc2_w  = (const float*)d_in[5];
    const float* fc2_b  = (const float*)d_in[6];
    const float* fc3_w  = (const float*)d_in[7];
    const float* fc3_b  = (const float*)d_in[8];
    const float* fc4_w  = (const float*)d_in[9];
    const float* fc4_b  = (const float*)d_in[10];
    const float* conv_w = (const float*)d_in[11];
    const float* conv_b = (const float*)d_in[12];
    const float* lfc_w  = (const float*)d_in[13];
    const float* lfc_b  = (const float*)d_in[14];
    float* out = (float*)d_out;

    float *p_nrm, *p_vol1, *p_vol2;
    bf16 *p_cubes, *p_xcat, *p_xl0, *p_h2, *p_h3, *p_wconv, *p_wlfc, *p_w2, *p_w3;
    cudaGetSymbolAddress((void**)&p_nrm, g_nrm);
    cudaGetSymbolAddress((void**)&p_vol1, g_vol1);
    cudaGetSymbolAddress((void**)&p_vol2, g_vol2);
    cudaGetSymbolAddress((void**)&p_cubes, g_cubes);
    cudaGetSymbolAddress((void**)&p_xcat, g_xcat);
    cudaGetSymbolAddress((void**)&p_xl0, g_xl0);
    cudaGetSymbolAddress((void**)&p_h2, g_h2);
    cudaGetSymbolAddress((void**)&p_h3, g_h3);
    cudaGetSymbolAddress((void**)&p_wconv, g_wconv);
    cudaGetSymbolAddress((void**)&p_wlfc, g_wlfc);
    cudaGetSymbolAddress((void**)&p_w2, g_w2);
    cudaGetSymbolAddress((void**)&p_w3, g_w3);

    cudaFuncSetAttribute(gemm_bf<0>, cudaFuncAttributeMaxDynamicSharedMemorySize, GEMM_SMEM);
    cudaFuncSetAttribute(gemm_bf<1>, cudaFuncAttributeMaxDynamicSharedMemorySize, GEMM_SMEM);

    // 1. normals
    k_zero<<<(NV * 3 + 255) / 256, 256>>>(p_nrm, NV * 3);
    k_face_normals<<<(NFACE + 255) / 256, 256>>>(v, f);

    // 2. volume pyramid
    k_down<<<(L1 * L1 * L1 + 255) / 256, 256>>>(volume, p_vol1, L1);
    k_down<<<(L2DIM * L2DIM * L2DIM + 255) / 256, 256>>>(p_vol1, p_vol2, L2DIM);

    // 3. weight prep (bf16, [N][K])
    k_prep_convw<<<(128 * KC + 255) / 256, 256>>>(conv_w);
    k_transpose<<<(128 * 128 + 255) / 256, 256>>>(lfc_w, p_wlfc, 128, 128);
    k_transpose<<<(256 * 512 + 255) / 256, 256>>>(fc2_w, p_w2, 256, 512);
    k_transpose<<<(512 * 256 + 255) / 256, 256>>>(fc3_w, p_w3, 512, 256);

    // 4. fc1 -> xcat[:, 0:128]
    k_fc1<<<NV, 128>>>(v, fc1_w, fc1_b);

    // 5. cube gather -> g_cubes [NV x 384] bf16
    k_gather<<<NV, 128>>>(v, volume);

    const int MB = (NV + 127) / 128;

    // 6. conv: cubes[NV,384] @ wconv^T -> xl0 [NV,128]
    gemm_bf<0><<<dim3(1, MB), 256, GEMM_SMEM>>>(p_cubes, p_wconv, conv_b, p_xl0, NV, 128, KC, 128);
    // 7. lfc: xl0 @ wlfc^T -> xcat[:, 128:256]
    gemm_bf<0><<<dim3(1, MB), 256, GEMM_SMEM>>>(p_xl0, p_wlfc, lfc_b, p_xcat + 128, NV, 128, 128, 256);
    // 8. fc2: xcat[NV,256] @ w2^T + b, leaky -> h2 [NV,512]
    gemm_bf<1><<<dim3(4, MB), 256, GEMM_SMEM>>>(p_xcat, p_w2, fc2_b, p_h2, NV, 512, 256, 512);
    // 9. fc3: h2[NV,512] @ w3^T + b, leaky -> h3 [NV,256]
    gemm_bf<1><<<dim3(2, MB), 256, GEMM_SMEM>>>(p_h2, p_w3, fc3_b, p_h3, NV, 256, 512, 256);

    // 10. fc4 + tanh*0.1 + coord
    k_fc4<<<(NV * 32 + 255) / 256, 256>>>(v, fc4_w, fc4_b, out);
}

// round 7
// speedup vs baseline: 4.1014x; 1.0963x over previous
#include <cuda_runtime.h>
#include <cuda_bf16.h>
#include <cstdint>
#include <math.h>

#define NV 150000
#define NFACE 300000
#define L0 192
#define L1 96
#define L2DIM 48
#define KC 384            // padded conv K (375 -> 384)

typedef __nv_bfloat16 bf16;

// ---------------- scratch (device globals; no allocation allowed) ----------
__device__ float g_nrm[NV * 3];
__device__ float g_vol1[L1 * L1 * L1];
__device__ float g_vol2[L2DIM * L2DIM * L2DIM];
__device__ bf16  g_cubes[(size_t)NV * KC];
__device__ bf16  g_xcat[(size_t)NV * 256];      // fc1 out | lfc out
__device__ bf16  g_h2[(size_t)NV * 512];
__device__ bf16  g_h3[(size_t)NV * 256];
// pre-transposed bf16 weights, layout [N][K]
__device__ bf16  g_wconv[128 * KC];
__device__ bf16  g_wlfc[128 * 128];
__device__ bf16  g_w2[512 * 256];
__device__ bf16  g_w3[256 * 512];

// ---------------- small kernels --------------------------------------------
__global__ void k_zero(float* p, int n) {
    int i = blockIdx.x * blockDim.x + threadIdx.x;
    if (i < n) p[i] = 0.f;
}

__global__ void k_face_normals(const float* __restrict__ v, const int* __restrict__ f) {
    int i = blockIdx.x * blockDim.x + threadIdx.x;
    if (i >= NFACE) return;
    int i0 = f[i * 3 + 0], i1 = f[i * 3 + 1], i2 = f[i * 3 + 2];
    float p0x = v[i0 * 3], p0y = v[i0 * 3 + 1], p0z = v[i0 * 3 + 2];
    float p1x = v[i1 * 3], p1y = v[i1 * 3 + 1], p1z = v[i1 * 3 + 2];
    float p2x = v[i2 * 3], p2y = v[i2 * 3 + 1], p2z = v[i2 * 3 + 2];
    float ax = p1x - p0x, ay = p1y - p0y, az = p1z - p0z;
    float bx = p2x - p0x, by = p2y - p0y, bz = p2z - p0z;
    float cx = ay * bz - az * by;
    float cy = az * bx - ax * bz;
    float cz = ax * by - ay * bx;
    atomicAdd(&g_nrm[i0 * 3 + 0], cx); atomicAdd(&g_nrm[i0 * 3 + 1], cy); atomicAdd(&g_nrm[i0 * 3 + 2], cz);
    atomicAdd(&g_nrm[i1 * 3 + 0], cx); atomicAdd(&g_nrm[i1 * 3 + 1], cy); atomicAdd(&g_nrm[i1 * 3 + 2], cz);
    atomicAdd(&g_nrm[i2 * 3 + 0], cx); atomicAdd(&g_nrm[i2 * 3 + 1], cy); atomicAdd(&g_nrm[i2 * 3 + 2], cz);
}

__global__ void k_down(const float* __restrict__ src, float* __restrict__ dst, int s) {
    int i = blockIdx.x * blockDim.x + threadIdx.x;
    int tot = s * s * s;
    if (i >= tot) return;
    int c = i % s, b = (i / s) % s, a = i / (s * s);
    int S = 2 * s;
    float sum = 0.f;
#pragma unroll
    for (int da = 0; da < 2; da++)
#pragma unroll
        for (int db = 0; db < 2; db++)
#pragma unroll
            for (int dc = 0; dc < 2; dc++)
                sum += src[((size_t)(2 * a + da) * S + (2 * b + db)) * S + (2 * c + dc)];
    dst[i] = sum * 0.125f;
}

// conv_w [128][375] fp32 -> g_wconv [128][384] bf16 (pad zeros)
__global__ void k_prep_convw(const float* __restrict__ w) {
    int i = blockIdx.x * blockDim.x + threadIdx.x;
    if (i >= 128 * KC) return;
    int o = i / KC, c = i % KC;
    g_wconv[i] = __float2bfloat16(c < 375 ? w[o * 375 + c] : 0.f);
}

// transpose fp32 [K][N] -> bf16 [N][K]
__global__ void k_transpose(const float* __restrict__ in, bf16* __restrict__ out, int K, int N) {
    int i = blockIdx.x * blockDim.x + threadIdx.x;
    if (i >= K * N) return;
    int n = i / K, k = i % K;
    out[i] = __float2bfloat16(in[(size_t)k * N + n]);
}

// fc1 (6->128) + leaky, weights cached in smem, grid-stride blocks
__global__ void k_fc1(const float* __restrict__ v, const float* __restrict__ w,
                      const float* __restrict__ b) {
    __shared__ float ws[6 * 128];
    __shared__ float bs[128];
    const int t = threadIdx.x;  // 128
    bs[t] = b[t];
#pragma unroll
    for (int i = 0; i < 6; i++) ws[i * 128 + t] = w[i * 128 + t];
    __syncthreads();
    for (int vid = blockIdx.x; vid < NV; vid += gridDim.x) {
        float in0 = v[vid * 3 + 0], in1 = v[vid * 3 + 1], in2 = v[vid * 3 + 2];
        float nx = g_nrm[vid * 3 + 0], ny = g_nrm[vid * 3 + 1], nz = g_nrm[vid * 3 + 2];
        float nn = fmaxf(sqrtf(nx * nx + ny * ny + nz * nz), 1e-12f);
        float acc = bs[t];
        acc += in0 * ws[t];
        acc += in1 * ws[128 + t];
        acc += in2 * ws[256 + t];
        acc += (nx / nn) * ws[384 + t];
        acc += (ny / nn) * ws[512 + t];
        acc += (nz / nn) * ws[640 + t];
        float r = acc > 0.f ? acc : 0.15f * acc;
        g_xcat[(size_t)vid * 256 + t] = __float2bfloat16(r);
    }
}

// gather 3-scale 5x5x5 cubes -> bf16 g_cubes[v][384]; 2 vertices per block
__global__ void k_gather(const float* __restrict__ v, const float* __restrict__ vol0) {
    int vid = blockIdx.x * 2 + (threadIdx.x >> 7);
    if (vid >= NV) return;
    int tl = threadIdx.x & 127;
    float vx = v[vid * 3 + 0], vy = v[vid * 3 + 1], vz = v[vid * 3 + 2];
    for (int c = tl; c < KC; c += 128) {
        float val = 0.f;
        if (c < 375) {
            int n = c / 125, r = c % 125;
            int di = r / 25, dj = (r / 5) % 5, dk = r % 5;
            const float* vol;
            int dim;
            float scale;
            if (n == 0)      { vol = vol0;   dim = L0;    scale = 96.f; }
            else if (n == 1) { vol = g_vol1; dim = L1;    scale = 48.f; }
            else             { vol = g_vol2; dim = L2DIM; scale = 24.f; }
            int hi = dim - 3;
            int i0 = min(max((int)rintf((vx + 1.f) * scale), 2), hi) + di - 2;
            int i1 = min(max((int)rintf((vy + 1.f) * scale), 2), hi) + dj - 2;
            int i2 = min(max((int)rintf((vz + 1.f) * scale), 2), hi) + dk - 2;
            val = vol[((size_t)i0 * dim + i1) * dim + i2];
        }
        g_cubes[(size_t)vid * KC + c] = __float2bfloat16(val);
    }
}

// ---------------- MMA building blocks --------------------------------------
__device__ __forceinline__ uint32_t smem_u32(const void* p) {
    uint32_t a;
    asm("{ .reg .u64 t; cvta.to.shared.u64 t, %1; cvt.u32.u64 %0, t; }" : "=r"(a) : "l"(p));
    return a;
}
__device__ __forceinline__ void mma_bf16(float c[4], const uint32_t a[4], const uint32_t b[2]) {
    asm volatile(
        "mma.sync.aligned.m16n8k16.row.col.f32.bf16.bf16.f32 "
        "{%0,%1,%2,%3}, {%4,%5,%6,%7}, {%8,%9}, {%0,%1,%2,%3};\n"
        : "+f"(c[0]), "+f"(c[1]), "+f"(c[2]), "+f"(c[3])
        : "r"(a[0]), "r"(a[1]), "r"(a[2]), "r"(a[3]), "r"(b[0]), "r"(b[1]));
}
__device__ __forceinline__ void ldsm_x4(uint32_t r[4], uint32_t addr) {
    asm volatile("ldmatrix.sync.aligned.m8n8.x4.shared.b16 {%0,%1,%2,%3}, [%4];"
                 : "=r"(r[0]), "=r"(r[1]), "=r"(r[2]), "=r"(r[3]) : "r"(addr));
}

// Stage geometry: A tiles (128x64 bf16 = 16KB) at sbase + s*16384 (s=0..2),
// B tiles at sbase + 49152 + s*16384. Row r of a tile: 8 16B chunks,
// chunk c stored at (c ^ (r&7)).
#define TILE_B 16384u
#define B_AREA 49152u
#define GEMM_SMEM (6 * 16384)

// cp.async one stage of A+B; A rows (bm+row) guarded vs M, B rows unguarded.
template <typename T>
__device__ __forceinline__ void issue_stage(uint32_t sbase, int stage,
                                            const T* A, const T* B,
                                            int bm, int bn, int M, int Kd,
                                            int k0, int t) {
#pragma unroll
    for (int i = 0; i < 4; i++) {
        int e = t + i * 256;
        int m = e >> 3, kc = e & 7;
        int gm = bm + m;
        int sz = (gm < M) ? 16 : 0;
        if (gm >= M) gm = M - 1;
        uint32_t dst = sbase + (uint32_t)stage * TILE_B + (uint32_t)m * 128u
                     + (uint32_t)((kc ^ (m & 7)) << 4);
        const void* src = A + (size_t)gm * Kd + k0 + kc * 8;
        asm volatile("cp.async.cg.shared.global [%0], [%1], 16, %2;"
                     :: "r"(dst), "l"(src), "r"(sz));
    }
#pragma unroll
    for (int i = 0; i < 4; i++) {
        int e = t + i * 256;
        int n = e >> 3, kc = e & 7;
        uint32_t dst = sbase + B_AREA + (uint32_t)stage * TILE_B + (uint32_t)n * 128u
                     + (uint32_t)((kc ^ (n & 7)) << 4);
        const void* src = B + (size_t)(bn + n) * Kd + k0 + kc * 8;
        asm volatile("cp.async.cg.shared.global [%0], [%1], 16;"
                     :: "r"(dst), "l"(src));
    }
    asm volatile("cp.async.commit_group;");
}

// one k-tile of MMA from smem tiles abase/bbase into acc
__device__ __forceinline__ void mma_tile(uint32_t abase, uint32_t bbase,
                                         float acc[4][4][4],
                                         int wm, int wn, int quad, int lrow) {
#pragma unroll
    for (int ks = 0; ks < 4; ks++) {
        const int kc0 = ks * 2 + (quad >> 1);
        uint32_t afr[4][4];
        uint32_t bfr[2][4];
#pragma unroll
        for (int im = 0; im < 4; im++) {
            int row = wm * 64 + im * 16 + (quad & 1) * 8 + lrow;
            uint32_t addr = abase + (uint32_t)row * 128u
                          + (uint32_t)((kc0 ^ (row & 7)) << 4);
            ldsm_x4(afr[im], addr);
        }
#pragma unroll
        for (int ib = 0; ib < 2; ib++) {
            int n = wn * 32 + ib * 16 + (quad & 1) * 8 + lrow;
            uint32_t addr = bbase + (uint32_t)n * 128u
                          + (uint32_t)((kc0 ^ (n & 7)) << 4);
            ldsm_x4(bfr[ib], addr);
        }
#pragma unroll
        for (int im = 0; im < 4; im++)
#pragma unroll
            for (int in = 0; in < 4; in++) {
                uint32_t bb[2] = { bfr[in >> 1][in & 1], bfr[in >> 1][2 + (in & 1)] };
                mma_bf16(acc[im][in], afr[im], bb);
            }
    }
}

// wait so that tile kt is ready, given issues up to min(nk-1, kt+2)
__device__ __forceinline__ void pipe_wait(int kt, int nk) {
    if (kt + 2 < nk)      asm volatile("cp.async.wait_group 2;");
    else if (kt + 1 < nk) asm volatile("cp.async.wait_group 1;");
    else                  asm volatile("cp.async.wait_group 0;");
}

// ---------------- generic bf16 GEMM (3-stage), for fc2/fc3 -----------------
template <int ACT>
__global__ __launch_bounds__(256)
void gemm_bf(const bf16* __restrict__ A, const bf16* __restrict__ B,
             const float* __restrict__ bias, bf16* __restrict__ C,
             int M, int N, int Kd, int ldc) {
    extern __shared__ char sm[];
    const int t = threadIdx.x;
    const int wid = t >> 5, lane = t & 31;
    const int wm = wid & 1, wn = wid >> 1;
    const int bm = blockIdx.y * 128, bn = blockIdx.x * 128;
    const uint32_t sbase = smem_u32(sm);
    const int quad = lane >> 3, lrow = lane & 7;

    float acc[4][4][4];
#pragma unroll
    for (int i = 0; i < 4; i++)
#pragma unroll
        for (int j = 0; j < 4; j++)
#pragma unroll
            for (int q = 0; q < 4; q++) acc[i][j][q] = 0.f;

    const int nk = Kd >> 6;
    issue_stage(sbase, 0, A, B, bm, bn, M, Kd, 0, t);
    if (nk > 1) issue_stage(sbase, 1, A, B, bm, bn, M, Kd, 64, t);

    for (int kt = 0; kt < nk; kt++) {
        const int s = kt % 3;
        if (kt + 2 < nk) issue_stage(sbase, (kt + 2) % 3, A, B, bm, bn, M, Kd, (kt + 2) * 64, t);
        pipe_wait(kt, nk);
        __syncthreads();
        mma_tile(sbase + (uint32_t)s * TILE_B, sbase + B_AREA + (uint32_t)s * TILE_B,
                 acc, wm, wn, quad, lrow);
        __syncthreads();
    }

    const int r = lane >> 2, c = lane & 3;
#pragma unroll
    for (int im = 0; im < 4; im++) {
        int gm0 = bm + wm * 64 + im * 16 + r;
#pragma unroll
        for (int in = 0; in < 4; in++) {
            int gn = bn + wn * 32 + in * 8 + c * 2;
            float b0 = bias[gn], b1 = bias[gn + 1];
            float v0 = acc[im][in][0] + b0;
            float v1 = acc[im][in][1] + b1;
            float v2 = acc[im][in][2] + b0;
            float v3 = acc[im][in][3] + b1;
            if (ACT == 1) {
                v0 = v0 > 0.f ? v0 : 0.15f * v0;
                v1 = v1 > 0.f ? v1 : 0.15f * v1;
                v2 = v2 > 0.f ? v2 : 0.15f * v2;
                v3 = v3 > 0.f ? v3 : 0.15f * v3;
            }
            if (gm0 < M) {
                __nv_bfloat162 p = __floats2bfloat162_rn(v0, v1);
                *reinterpret_cast<uint32_t*>(C + (size_t)gm0 * ldc + gn) =
                    *reinterpret_cast<uint32_t*>(&p);
            }
            if (gm0 + 8 < M) {
                __nv_bfloat162 p = __floats2bfloat162_rn(v2, v3);
                *reinterpret_cast<uint32_t*>(C + (size_t)(gm0 + 8) * ldc + gn) =
                    *reinterpret_cast<uint32_t*>(&p);
            }
        }
    }
}

// ---------------- fused conv (K=384) + lfc (K=128) kernel ------------------
// conv: cubes[128 rows] @ wconv^T + conv_b -> 128x128 bf16 kept in SMEM
// lfc:  that tile @ wlfc^T + lfc_b -> xcat[:,128:256]
__global__ __launch_bounds__(256)
void k_convlfc(const bf16* __restrict__ Acub, const bf16* __restrict__ Wconv,
               const float* __restrict__ conv_b,
               const bf16* __restrict__ Wlfc, const float* __restrict__ lfc_b,
               bf16* __restrict__ xcat, int M) {
    extern __shared__ char sm[];
    const int t = threadIdx.x;
    const int wid = t >> 5, lane = t & 31;
    const int wm = wid & 1, wn = wid >> 1;
    const int bm = blockIdx.y * 128;
    const uint32_t sbase = smem_u32(sm);
    const int quad = lane >> 3, lrow = lane & 7;
    const int r = lane >> 2, c = lane & 3;

    float acc[4][4][4];
#pragma unroll
    for (int i = 0; i < 4; i++)
#pragma unroll
        for (int j = 0; j < 4; j++)
#pragma unroll
            for (int q = 0; q < 4; q++) acc[i][j][q] = 0.f;

    // ---- conv GEMM: nk = 6 k-tiles ----
    const int nk = KC >> 6;
    issue_stage(sbase, 0, Acub, Wconv, bm, 0, M, KC, 0, t);
    issue_stage(sbase, 1, Acub, Wconv, bm, 0, M, KC, 64, t);
    for (int kt = 0; kt < nk; kt++) {
        const int s = kt % 3;
        if (kt + 2 < nk) issue_stage(sbase, (kt + 2) % 3, Acub, Wconv, bm, 0, M, KC, (kt + 2) * 64, t);
        pipe_wait(kt, nk);
        __syncthreads();
        mma_tile(sbase + (uint32_t)s * TILE_B, sbase + B_AREA + (uint32_t)s * TILE_B,
                 acc, wm, wn, quad, lrow);
        __syncthreads();
    }
    asm volatile("cp.async.wait_group 0;");
    __syncthreads();

    // ---- store conv result (+bias, bf16) into A stages 0/1, swizzled ----
#pragma unroll
    for (int im = 0; im < 4; im++) {
#pragma unroll
        for (int in = 0; in < 4; in++) {
            int n = wn * 32 + in * 8 + c * 2;
            float b0 = conv_b[n], b1 = conv_b[n + 1];
            int tile = n >> 6;
            int bcol = (n & 63) * 2;
            int chunk = bcol >> 4, within = bcol & 15;
#pragma unroll
            for (int half = 0; half < 2; half++) {
                int m = wm * 64 + im * 16 + r + half * 8;
                float v0 = acc[im][in][2 * half] + b0;
                float v1 = acc[im][in][2 * half + 1] + b1;
                __nv_bfloat162 p = __floats2bfloat162_rn(v0, v1);
                uint32_t addr = sbase + (uint32_t)tile * TILE_B + (uint32_t)m * 128u
                              + (uint32_t)((chunk ^ (m & 7)) << 4) + (uint32_t)within;
                asm volatile("st.shared.b32 [%0], %1;" :: "r"(addr),
                             "r"(*reinterpret_cast<uint32_t*>(&p)));
            }
        }
    }

    // ---- load wlfc (128x128) into B stages 0/1 ----
#pragma unroll
    for (int kt = 0; kt < 2; kt++) {
#pragma unroll
        for (int i = 0; i < 4; i++) {
            int e = t + i * 256;
            int n = e >> 3, kc = e & 7;
            uint32_t dst = sbase + B_AREA + (uint32_t)kt * TILE_B + (uint32_t)n * 128u
                         + (uint32_t)((kc ^ (n & 7)) << 4);
            const void* src = Wlfc + (size_t)n * 128 + kt * 64 + kc * 8;
            asm volatile("cp.async.cg.shared.global [%0], [%1], 16;"
                         :: "r"(dst), "l"(src));
        }
    }
    asm volatile("cp.async.commit_group;");
    asm volatile("cp.async.wait_group 0;");
    __syncthreads();

    // ---- lfc GEMM: 2 k-tiles from smem ----
    float acc2[4][4][4];
#pragma unroll
    for (int i = 0; i < 4; i++)
#pragma unroll
        for (int j = 0; j < 4; j++)
#pragma unroll
            for (int q = 0; q < 4; q++) acc2[i][j][q] = 0.f;
#pragma unroll
    for (int kt = 0; kt < 2; kt++)
        mma_tile(sbase + (uint32_t)kt * TILE_B, sbase + B_AREA + (uint32_t)kt * TILE_B,
                 acc2, wm, wn, quad, lrow);

    // ---- epilogue to xcat[:,128:256] (ldc = 256) ----
#pragma unroll
    for (int im = 0; im < 4; im++) {
        int gm0 = bm + wm * 64 + im * 16 + r;
#pragma unroll
        for (int in = 0; in < 4; in++) {
            int gn = wn * 32 + in * 8 + c * 2;
            float b0 = lfc_b[gn], b1 = lfc_b[gn + 1];
            float v0 = acc2[im][in][0] + b0;
            float v1 = acc2[im][in][1] + b1;
            float v2 = acc2[im][in][2] + b0;
            float v3 = acc2[im][in][3] + b1;
            if (gm0 < M) {
                __nv_bfloat162 p = __floats2bfloat162_rn(v0, v1);
                *reinterpret_cast<uint32_t*>(xcat + (size_t)gm0 * 256 + 128 + gn) =
                    *reinterpret_cast<uint32_t*>(&p);
            }
            if (gm0 + 8 < M) {
                __nv_bfloat162 p = __floats2bfloat162_rn(v2, v3);
                *reinterpret_cast<uint32_t*>(xcat + (size_t)(gm0 + 8) * 256 + 128 + gn) =
                    *reinterpret_cast<uint32_t*>(&p);
            }
        }
    }
}

// fc4: 256 -> 3 from bf16 h3, tanh * 0.1, + coord. One warp per vertex.
__global__ void k_fc4(const float* __restrict__ v, const float* __restrict__ w,
                      const float* __restrict__ b, float* __restrict__ out) {
    int gtid = blockIdx.x * blockDim.x + threadIdx.x;
    int vert = gtid >> 5;
    int lane = threadIdx.x & 31;
    if (vert >= NV) return;
    const bf16* h = g_h3 + (size_t)vert * 256;
    float s0 = 0.f, s1 = 0.f, s2 = 0.f;
#pragma unroll
    for (int i = 0; i < 8; i++) {
        int k = lane + i * 32;
        float x = __bfloat162float(h[k]);
        s0 += x * w[k * 3 + 0];
        s1 += x * w[k * 3 + 1];
        s2 += x * w[k * 3 + 2];
    }
#pragma unroll
    for (int off = 16; off > 0; off >>= 1) {
        s0 += __shfl_down_sync(0xFFFFFFFFu, s0, off);
        s1 += __shfl_down_sync(0xFFFFFFFFu, s1, off);
        s2 += __shfl_down_sync(0xFFFFFFFFu, s2, off);
    }
    if (lane == 0) {
        out[vert * 3 + 0] = v[vert * 3 + 0] + 0.1f * tanhf(s0 + b[0]);
        out[vert * 3 + 1] = v[vert * 3 + 1] + 0.1f * tanhf(s1 + b[1]);
        out[vert * 3 + 2] = v[vert * 3 + 2] + 0.1f * tanhf(s2 + b[2]);
    }
}

// ---------------- launch ----------------------------------------------------
extern "C" void kernel_launch(void* const* d_in, const int* in_sizes, int n_in,
                              void* d_out, int out_size) {
    const float* v      = (const float*)d_in[0];
    const int*   f      = (const int*)d_in[1];
    const float* volume = (const float*)d_in[2];
    const float* fc1_w  = (const float*)d_in[3];
    const float* fc1_b  = (const float*)d_in[4];
    const float* fc2_w  = (const float*)d_in[5];
    const float* fc2_b  = (const float*)d_in[6];
    const float* fc3_w  = (const float*)d_in[7];
    const float* fc3_b  = (const float*)d_in[8];
    const float* fc4_w  = (const float*)d_in[9];
    const float* fc4_b  = (const float*)d_in[10];
    const float* conv_w = (const float*)d_in[11];
    const float* conv_b = (const float*)d_in[12];
    const float* lfc_w  = (const float*)d_in[13];
    const float* lfc_b  = (const float*)d_in[14];
    float* out = (float*)d_out;

    float *p_nrm, *p_vol1, *p_vol2;
    bf16 *p_cubes, *p_xcat, *p_h2, *p_h3, *p_wconv, *p_wlfc, *p_w2, *p_w3;
    cudaGetSymbolAddress((void**)&p_nrm, g_nrm);
    cudaGetSymbolAddress((void**)&p_vol1, g_vol1);
    cudaGetSymbolAddress((void**)&p_vol2, g_vol2);
    cudaGetSymbolAddress((void**)&p_cubes, g_cubes);
    cudaGetSymbolAddress((void**)&p_xcat, g_xcat);
    cudaGetSymbolAddress((void**)&p_h2, g_h2);
    cudaGetSymbolAddress((void**)&p_h3, g_h3);
    cudaGetSymbolAddress((void**)&p_wconv, g_wconv);
    cudaGetSymbolAddress((void**)&p_wlfc, g_wlfc);
    cudaGetSymbolAddress((void**)&p_w2, g_w2);
    cudaGetSymbolAddress((void**)&p_w3, g_w3);

    cudaFuncSetAttribute(gemm_bf<0>, cudaFuncAttributeMaxDynamicSharedMemorySize, GEMM_SMEM);
    cudaFuncSetAttribute(gemm_bf<1>, cudaFuncAttributeMaxDynamicSharedMemorySize, GEMM_SMEM);
    cudaFuncSetAttribute(k_convlfc, cudaFuncAttributeMaxDynamicSharedMemorySize, GEMM_SMEM);

    // 1. normals
    k_zero<<<(NV * 3 + 255) / 256, 256>>>(p_nrm, NV * 3);
    k_face_normals<<<(NFACE + 255) / 256, 256>>>(v, f);

    // 2. volume pyramid
    k_down<<<(L1 * L1 * L1 + 255) / 256, 256>>>(volume, p_vol1, L1);
    k_down<<<(L2DIM * L2DIM * L2DIM + 255) / 256, 256>>>(p_vol1, p_vol2, L2DIM);

    // 3. weight prep (bf16, [N][K])
    k_prep_convw<<<(128 * KC + 255) / 256, 256>>>(conv_w);
    k_transpose<<<(128 * 128 + 255) / 256, 256>>>(lfc_w, p_wlfc, 128, 128);
    k_transpose<<<(256 * 512 + 255) / 256, 256>>>(fc2_w, p_w2, 256, 512);
    k_transpose<<<(512 * 256 + 255) / 256, 256>>>(fc3_w, p_w3, 512, 256);

    // 4. fc1 -> xcat[:, 0:128]
    k_fc1<<<1184, 128>>>(v, fc1_w, fc1_b);

    // 5. cube gather -> g_cubes [NV x 384] bf16
    k_gather<<<(NV + 1) / 2, 256>>>(v, volume);

    const int MB = (NV + 127) / 128;

    // 6+7. fused conv + lfc -> xcat[:, 128:256]
    k_convlfc<<<dim3(1, MB), 256, GEMM_SMEM>>>(p_cubes, p_wconv, conv_b,
                                               p_wlfc, lfc_b, p_xcat, NV);
    // 8. fc2: xcat[NV,256] @ w2^T + b, leaky -> h2 [NV,512]
    gemm_bf<1><<<dim3(4, MB), 256, GEMM_SMEM>>>(p_xcat, p_w2, fc2_b, p_h2, NV, 512, 256, 512);
    // 9. fc3: h2[NV,512] @ w3^T + b, leaky -> h3 [NV,256]
    gemm_bf<1><<<dim3(2, MB), 256, GEMM_SMEM>>>(p_h2, p_w3, fc3_b, p_h3, NV, 256, 512, 256);

    // 10. fc4 + tanh*0.1 + coord
    k_fc4<<<(NV * 32 + 255) / 256, 256>>>(v, fc4_w, fc4_b, out);
}

// round 8
// speedup vs baseline: 4.1943x; 1.0226x over previous
#include <cuda_runtime.h>
#include <cuda_bf16.h>
#include <cstdint>
#include <math.h>

#define NV 150000
#define NFACE 300000
#define L0 192
#define L1 96
#define L2DIM 48
#define KC 384            // padded conv K (375 -> 384)

typedef __nv_bfloat16 bf16;

// ---------------- scratch (device globals; no allocation allowed) ----------
__device__ float g_nrm[NV * 3];
__device__ float g_s[NV * 3];                   // fc4 staging accumulator
__device__ float g_vol1[L1 * L1 * L1];
__device__ float g_vol2[L2DIM * L2DIM * L2DIM];
__device__ bf16  g_cubes[(size_t)NV * KC];
__device__ bf16  g_xcat[(size_t)NV * 256];      // fc1 out | lfc out
__device__ bf16  g_h2[(size_t)NV * 512];
// pre-transposed bf16 weights, layout [N][K]
__device__ bf16  g_wconv[128 * KC];
__device__ bf16  g_wlfc[128 * 128];
__device__ bf16  g_w2[512 * 256];
__device__ bf16  g_w3[256 * 512];

// ---------------- small kernels --------------------------------------------
__global__ void k_zero(float* p, int n) {
    int i = blockIdx.x * blockDim.x + threadIdx.x;
    if (i < n) p[i] = 0.f;
}

__global__ void k_face_normals(const float* __restrict__ v, const int* __restrict__ f) {
    int i = blockIdx.x * blockDim.x + threadIdx.x;
    if (i >= NFACE) return;
    int i0 = f[i * 3 + 0], i1 = f[i * 3 + 1], i2 = f[i * 3 + 2];
    float p0x = v[i0 * 3], p0y = v[i0 * 3 + 1], p0z = v[i0 * 3 + 2];
    float p1x = v[i1 * 3], p1y = v[i1 * 3 + 1], p1z = v[i1 * 3 + 2];
    float p2x = v[i2 * 3], p2y = v[i2 * 3 + 1], p2z = v[i2 * 3 + 2];
    float ax = p1x - p0x, ay = p1y - p0y, az = p1z - p0z;
    float bx = p2x - p0x, by = p2y - p0y, bz = p2z - p0z;
    float cx = ay * bz - az * by;
    float cy = az * bx - ax * bz;
    float cz = ax * by - ay * bx;
    atomicAdd(&g_nrm[i0 * 3 + 0], cx); atomicAdd(&g_nrm[i0 * 3 + 1], cy); atomicAdd(&g_nrm[i0 * 3 + 2], cz);
    atomicAdd(&g_nrm[i1 * 3 + 0], cx); atomicAdd(&g_nrm[i1 * 3 + 1], cy); atomicAdd(&g_nrm[i1 * 3 + 2], cz);
    atomicAdd(&g_nrm[i2 * 3 + 0], cx); atomicAdd(&g_nrm[i2 * 3 + 1], cy); atomicAdd(&g_nrm[i2 * 3 + 2], cz);
}

__global__ void k_down(const float* __restrict__ src, float* __restrict__ dst, int s) {
    int i = blockIdx.x * blockDim.x + threadIdx.x;
    int tot = s * s * s;
    if (i >= tot) return;
    int c = i % s, b = (i / s) % s, a = i / (s * s);
    int S = 2 * s;
    float sum = 0.f;
#pragma unroll
    for (int da = 0; da < 2; da++)
#pragma unroll
        for (int db = 0; db < 2; db++)
#pragma unroll
            for (int dc = 0; dc < 2; dc++)
                sum += src[((size_t)(2 * a + da) * S + (2 * b + db)) * S + (2 * c + dc)];
    dst[i] = sum * 0.125f;
}

// merged weight prep: conv pad + 3 transposes, one launch
#define PREP_N0 (128 * KC)
#define PREP_N1 (PREP_N0 + 128 * 128)
#define PREP_N2 (PREP_N1 + 512 * 256)
#define PREP_N3 (PREP_N2 + 256 * 512)
__global__ void k_prep(const float* __restrict__ conv_w, const float* __restrict__ lfc_w,
                       const float* __restrict__ fc2_w, const float* __restrict__ fc3_w) {
    int i = blockIdx.x * blockDim.x + threadIdx.x;
    if (i < PREP_N0) {
        int o = i / KC, c = i % KC;
        g_wconv[i] = __float2bfloat16(c < 375 ? conv_w[o * 375 + c] : 0.f);
    } else if (i < PREP_N1) {
        int j = i - PREP_N0;              // [N=128][K=128] from lfc_w[K=128][N=128]
        int n = j / 128, k = j % 128;
        g_wlfc[j] = __float2bfloat16(lfc_w[(size_t)k * 128 + n]);
    } else if (i < PREP_N2) {
        int j = i - PREP_N1;              // [N=512][K=256] from fc2_w[256][512]
        int n = j / 256, k = j % 256;
        g_w2[j] = __float2bfloat16(fc2_w[(size_t)k * 512 + n]);
    } else if (i < PREP_N3) {
        int j = i - PREP_N2;              // [N=256][K=512] from fc3_w[512][256]
        int n = j / 512, k = j % 512;
        g_w3[j] = __float2bfloat16(fc3_w[(size_t)k * 256 + n]);
    }
}

// fc1 (6->128) + leaky, weights cached in smem, grid-stride blocks
__global__ void k_fc1(const float* __restrict__ v, const float* __restrict__ w,
                      const float* __restrict__ b) {
    __shared__ float ws[6 * 128];
    __shared__ float bs[128];
    const int t = threadIdx.x;  // 128
    bs[t] = b[t];
#pragma unroll
    for (int i = 0; i < 6; i++) ws[i * 128 + t] = w[i * 128 + t];
    __syncthreads();
    for (int vid = blockIdx.x; vid < NV; vid += gridDim.x) {
        float in0 = v[vid * 3 + 0], in1 = v[vid * 3 + 1], in2 = v[vid * 3 + 2];
        float nx = g_nrm[vid * 3 + 0], ny = g_nrm[vid * 3 + 1], nz = g_nrm[vid * 3 + 2];
        float nn = fmaxf(sqrtf(nx * nx + ny * ny + nz * nz), 1e-12f);
        float acc = bs[t];
        acc += in0 * ws[t];
        acc += in1 * ws[128 + t];
        acc += in2 * ws[256 + t];
        acc += (nx / nn) * ws[384 + t];
        acc += (ny / nn) * ws[512 + t];
        acc += (nz / nn) * ws[640 + t];
        float r = acc > 0.f ? acc : 0.15f * acc;
        g_xcat[(size_t)vid * 256 + t] = __float2bfloat16(r);
    }
}

// gather 3-scale 5x5x5 cubes -> bf16 g_cubes[v][384]; 2 vertices per block
// (pad cols 375..383 of g_cubes stay at their load-time zero init: never written)
__global__ void k_gather(const float* __restrict__ v, const float* __restrict__ vol0) {
    int vid = blockIdx.x * 2 + (threadIdx.x >> 7);
    if (vid >= NV) return;
    int tl = threadIdx.x & 127;
    float vx = v[vid * 3 + 0], vy = v[vid * 3 + 1], vz = v[vid * 3 + 2];
    for (int c = tl; c < 375; c += 128) {
        int n = c / 125, r = c % 125;
        int di = r / 25, dj = (r / 5) % 5, dk = r % 5;
        const float* vol;
        int dim;
        float scale;
        if (n == 0)      { vol = vol0;   dim = L0;    scale = 96.f; }
        else if (n == 1) { vol = g_vol1; dim = L1;    scale = 48.f; }
        else             { vol = g_vol2; dim = L2DIM; scale = 24.f; }
        int hi = dim - 3;
        int i0 = min(max((int)rintf((vx + 1.f) * scale), 2), hi) + di - 2;
        int i1 = min(max((int)rintf((vy + 1.f) * scale), 2), hi) + dj - 2;
        int i2 = min(max((int)rintf((vz + 1.f) * scale), 2), hi) + dk - 2;
        float val = vol[((size_t)i0 * dim + i1) * dim + i2];
        g_cubes[(size_t)vid * KC + c] = __float2bfloat16(val);
    }
}

// ---------------- MMA building blocks --------------------------------------
__device__ __forceinline__ uint32_t smem_u32(const void* p) {
    uint32_t a;
    asm("{ .reg .u64 t; cvta.to.shared.u64 t, %1; cvt.u32.u64 %0, t; }" : "=r"(a) : "l"(p));
    return a;
}
__device__ __forceinline__ void mma_bf16(float c[4], const uint32_t a[4], const uint32_t b[2]) {
    asm volatile(
        "mma.sync.aligned.m16n8k16.row.col.f32.bf16.bf16.f32 "
        "{%0,%1,%2,%3}, {%4,%5,%6,%7}, {%8,%9}, {%0,%1,%2,%3};\n"
        : "+f"(c[0]), "+f"(c[1]), "+f"(c[2]), "+f"(c[3])
        : "r"(a[0]), "r"(a[1]), "r"(a[2]), "r"(a[3]), "r"(b[0]), "r"(b[1]));
}
__device__ __forceinline__ void ldsm_x4(uint32_t r[4], uint32_t addr) {
    asm volatile("ldmatrix.sync.aligned.m8n8.x4.shared.b16 {%0,%1,%2,%3}, [%4];"
                 : "=r"(r[0]), "=r"(r[1]), "=r"(r[2]), "=r"(r[3]) : "r"(addr));
}

// Stage geometry: A tiles (128x64 bf16 = 16KB) at sbase + s*16384 (s=0..2),
// B tiles at sbase + 49152 + s*16384. Row r of a tile: 8 16B chunks,
// chunk c stored at (c ^ (r&7)).
#define TILE_B 16384u
#define B_AREA 49152u
#define SPART_OFF 98304u
#define GEMM_SMEM (98304 + 1536)

// cp.async one stage of A+B; A rows (bm+row) guarded vs M, B rows unguarded.
template <typename T>
__device__ __forceinline__ void issue_stage(uint32_t sbase, int stage,
                                            const T* A, const T* B,
                                            int bm, int bn, int M, int Kd,
                                            int k0, int t) {
#pragma unroll
    for (int i = 0; i < 4; i++) {
        int e = t + i * 256;
        int m = e >> 3, kc = e & 7;
        int gm = bm + m;
        int sz = (gm < M) ? 16 : 0;
        if (gm >= M) gm = M - 1;
        uint32_t dst = sbase + (uint32_t)stage * TILE_B + (uint32_t)m * 128u
                     + (uint32_t)((kc ^ (m & 7)) << 4);
        const void* src = A + (size_t)gm * Kd + k0 + kc * 8;
        asm volatile("cp.async.cg.shared.global [%0], [%1], 16, %2;"
                     :: "r"(dst), "l"(src), "r"(sz));
    }
#pragma unroll
    for (int i = 0; i < 4; i++) {
        int e = t + i * 256;
        int n = e >> 3, kc = e & 7;
        uint32_t dst = sbase + B_AREA + (uint32_t)stage * TILE_B + (uint32_t)n * 128u
                     + (uint32_t)((kc ^ (n & 7)) << 4);
        const void* src = B + (size_t)(bn + n) * Kd + k0 + kc * 8;
        asm volatile("cp.async.cg.shared.global [%0], [%1], 16;"
                     :: "r"(dst), "l"(src));
    }
    asm volatile("cp.async.commit_group;");
}

// one k-tile of MMA from smem tiles abase/bbase into acc
__device__ __forceinline__ void mma_tile(uint32_t abase, uint32_t bbase,
                                         float acc[4][4][4],
                                         int wm, int wn, int quad, int lrow) {
#pragma unroll
    for (int ks = 0; ks < 4; ks++) {
        const int kc0 = ks * 2 + (quad >> 1);
        uint32_t afr[4][4];
        uint32_t bfr[2][4];
#pragma unroll
        for (int im = 0; im < 4; im++) {
            int row = wm * 64 + im * 16 + (quad & 1) * 8 + lrow;
            uint32_t addr = abase + (uint32_t)row * 128u
                          + (uint32_t)((kc0 ^ (row & 7)) << 4);
            ldsm_x4(afr[im], addr);
        }
#pragma unroll
        for (int ib = 0; ib < 2; ib++) {
            int n = wn * 32 + ib * 16 + (quad & 1) * 8 + lrow;
            uint32_t addr = bbase + (uint32_t)n * 128u
                          + (uint32_t)((kc0 ^ (n & 7)) << 4);
            ldsm_x4(bfr[ib], addr);
        }
#pragma unroll
        for (int im = 0; im < 4; im++)
#pragma unroll
            for (int in = 0; in < 4; in++) {
                uint32_t bb[2] = { bfr[in >> 1][in & 1], bfr[in >> 1][2 + (in & 1)] };
                mma_bf16(acc[im][in], afr[im], bb);
            }
    }
}

// wait so that tile kt is ready, given issues up to min(nk-1, kt+2)
__device__ __forceinline__ void pipe_wait(int kt, int nk) {
    if (kt + 2 < nk)      asm volatile("cp.async.wait_group 2;");
    else if (kt + 1 < nk) asm volatile("cp.async.wait_group 1;");
    else                  asm volatile("cp.async.wait_group 0;");
}

// ---------------- generic bf16 GEMM (3-stage) -------------------------------
// FUSE=0: C = act(A@B^T + bias). FUSE=1 (fc3+fc4): no C store; instead
// s_out[row][j] += sum_n leaky(acc+bias)[row][n] * w4[n][j] (j=0..2).
template <int ACT, int FUSE>
__global__ __launch_bounds__(256)
void gemm_bf(const bf16* __restrict__ A, const bf16* __restrict__ B,
             const float* __restrict__ bias, bf16* __restrict__ C,
             int M, int N, int Kd, int ldc,
             const float* __restrict__ w4, float* __restrict__ s_out) {
    extern __shared__ char sm[];
    const int t = threadIdx.x;
    const int wid = t >> 5, lane = t & 31;
    const int wm = wid & 1, wn = wid >> 1;
    const int bm = blockIdx.y * 128, bn = blockIdx.x * 128;
    const uint32_t sbase = smem_u32(sm);
    const int quad = lane >> 3, lrow = lane & 7;

    float acc[4][4][4];
#pragma unroll
    for (int i = 0; i < 4; i++)
#pragma unroll
        for (int j = 0; j < 4; j++)
#pragma unroll
            for (int q = 0; q < 4; q++) acc[i][j][q] = 0.f;

    const int nk = Kd >> 6;
    issue_stage(sbase, 0, A, B, bm, bn, M, Kd, 0, t);
    if (nk > 1) issue_stage(sbase, 1, A, B, bm, bn, M, Kd, 64, t);

    for (int kt = 0; kt < nk; kt++) {
        const int s = kt % 3;
        if (kt + 2 < nk) issue_stage(sbase, (kt + 2) % 3, A, B, bm, bn, M, Kd, (kt + 2) * 64, t);
        pipe_wait(kt, nk);
        __syncthreads();
        mma_tile(sbase + (uint32_t)s * TILE_B, sbase + B_AREA + (uint32_t)s * TILE_B,
                 acc, wm, wn, quad, lrow);
        __syncthreads();
    }

    const int r = lane >> 2, c = lane & 3;

    if (FUSE == 0) {
#pragma unroll
        for (int im = 0; im < 4; im++) {
            int gm0 = bm + wm * 64 + im * 16 + r;
#pragma unroll
            for (int in = 0; in < 4; in++) {
                int gn = bn + wn * 32 + in * 8 + c * 2;
                float b0 = bias[gn], b1 = bias[gn + 1];
                float v0 = acc[im][in][0] + b0;
                float v1 = acc[im][in][1] + b1;
                float v2 = acc[im][in][2] + b0;
                float v3 = acc[im][in][3] + b1;
                if (ACT == 1) {
                    v0 = v0 > 0.f ? v0 : 0.15f * v0;
                    v1 = v1 > 0.f ? v1 : 0.15f * v1;
                    v2 = v2 > 0.f ? v2 : 0.15f * v2;
                    v3 = v3 > 0.f ? v3 : 0.15f * v3;
                }
                if (gm0 < M) {
                    __nv_bfloat162 p = __floats2bfloat162_rn(v0, v1);
                    *reinterpret_cast<uint32_t*>(C + (size_t)gm0 * ldc + gn) =
                        *reinterpret_cast<uint32_t*>(&p);
                }
                if (gm0 + 8 < M) {
                    __nv_bfloat162 p = __floats2bfloat162_rn(v2, v3);
                    *reinterpret_cast<uint32_t*>(C + (size_t)(gm0 + 8) * ldc + gn) =
                        *reinterpret_cast<uint32_t*>(&p);
                }
            }
        }
    } else {
        // fused fc4 reduction
        float* s_part = reinterpret_cast<float*>(sm + SPART_OFF);  // [128][3]
        for (int i = t; i < 384; i += 256) s_part[i] = 0.f;
        // per-thread w4 rows and biases (8 n-values)
        float w4r[8][3], br[8];
#pragma unroll
        for (int in = 0; in < 4; in++)
#pragma unroll
            for (int p = 0; p < 2; p++) {
                int n = bn + wn * 32 + in * 8 + c * 2 + p;
                w4r[in * 2 + p][0] = w4[n * 3 + 0];
                w4r[in * 2 + p][1] = w4[n * 3 + 1];
                w4r[in * 2 + p][2] = w4[n * 3 + 2];
                br[in * 2 + p] = bias[n];
            }
        __syncthreads();
#pragma unroll
        for (int im = 0; im < 4; im++) {
#pragma unroll
            for (int half = 0; half < 2; half++) {
                int rowl = wm * 64 + im * 16 + r + half * 8;
                float s0 = 0.f, s1 = 0.f, s2 = 0.f;
#pragma unroll
                for (int in = 0; in < 4; in++)
#pragma unroll
                    for (int p = 0; p < 2; p++) {
                        float val = acc[im][in][half * 2 + p] + br[in * 2 + p];
                        val = val > 0.f ? val : 0.15f * val;
                        s0 += val * w4r[in * 2 + p][0];
                        s1 += val * w4r[in * 2 + p][1];
                        s2 += val * w4r[in * 2 + p][2];
                    }
                atomicAdd(&s_part[rowl * 3 + 0], s0);
                atomicAdd(&s_part[rowl * 3 + 1], s1);
                atomicAdd(&s_part[rowl * 3 + 2], s2);
            }
        }
        __syncthreads();
        for (int i = t; i < 384; i += 256) {
            int gm = bm + i / 3;
            if (gm < M) atomicAdd(&s_out[(size_t)gm * 3 + i % 3], s_part[i]);
        }
    }
}

// ---------------- fused conv (K=384) + lfc (K=128) kernel ------------------
__global__ __launch_bounds__(256)
void k_convlfc(const bf16* __restrict__ Acub, const bf16* __restrict__ Wconv,
               const float* __restrict__ conv_b,
               const bf16* __restrict__ Wlfc, const float* __restrict__ lfc_b,
               bf16* __restrict__ xcat, int M) {
    extern __shared__ char sm[];
    const int t = threadIdx.x;
    const int wid = t >> 5, lane = t & 31;
    const int wm = wid & 1, wn = wid >> 1;
    const int bm = blockIdx.y * 128;
    const uint32_t sbase = smem_u32(sm);
    const int quad = lane >> 3, lrow = lane & 7;
    const int r = lane >> 2, c = lane & 3;

    float acc[4][4][4];
#pragma unroll
    for (int i = 0; i < 4; i++)
#pragma unroll
        for (int j = 0; j < 4; j++)
#pragma unroll
            for (int q = 0; q < 4; q++) acc[i][j][q] = 0.f;

    // ---- conv GEMM: nk = 6 k-tiles ----
    const int nk = KC >> 6;
    issue_stage(sbase, 0, Acub, Wconv, bm, 0, M, KC, 0, t);
    issue_stage(sbase, 1, Acub, Wconv, bm, 0, M, KC, 64, t);
    for (int kt = 0; kt < nk; kt++) {
        const int s = kt % 3;
        if (kt + 2 < nk) issue_stage(sbase, (kt + 2) % 3, Acub, Wconv, bm, 0, M, KC, (kt + 2) * 64, t);
        pipe_wait(kt, nk);
        __syncthreads();
        mma_tile(sbase + (uint32_t)s * TILE_B, sbase + B_AREA + (uint32_t)s * TILE_B,
                 acc, wm, wn, quad, lrow);
        __syncthreads();
    }
    asm volatile("cp.async.wait_group 0;");
    __syncthreads();

    // ---- store conv result (+bias, bf16) into A stages 0/1, swizzled ----
#pragma unroll
    for (int im = 0; im < 4; im++) {
#pragma unroll
        for (int in = 0; in < 4; in++) {
            int n = wn * 32 + in * 8 + c * 2;
            float b0 = conv_b[n], b1 = conv_b[n + 1];
            int tile = n >> 6;
            int bcol = (n & 63) * 2;
            int chunk = bcol >> 4, within = bcol & 15;
#pragma unroll
            for (int half = 0; half < 2; half++) {
                int m = wm * 64 + im * 16 + r + half * 8;
                float v0 = acc[im][in][2 * half] + b0;
                float v1 = acc[im][in][2 * half + 1] + b1;
                __nv_bfloat162 p = __floats2bfloat162_rn(v0, v1);
                uint32_t addr = sbase + (uint32_t)tile * TILE_B + (uint32_t)m * 128u
                              + (uint32_t)((chunk ^ (m & 7)) << 4) + (uint32_t)within;
                asm volatile("st.shared.b32 [%0], %1;" :: "r"(addr),
                             "r"(*reinterpret_cast<uint32_t*>(&p)));
            }
        }
    }

    // ---- load wlfc (128x128) into B stages 0/1 ----
#pragma unroll
    for (int kt = 0; kt < 2; kt++) {
#pragma unroll
        for (int i = 0; i < 4; i++) {
            int e = t + i * 256;
            int n = e >> 3, kc = e & 7;
            uint32_t dst = sbase + B_AREA + (uint32_t)kt * TILE_B + (uint32_t)n * 128u
                         + (uint32_t)((kc ^ (n & 7)) << 4);
            const void* src = Wlfc + (size_t)n * 128 + kt * 64 + kc * 8;
            asm volatile("cp.async.cg.shared.global [%0], [%1], 16;"
                         :: "r"(dst), "l"(src));
        }
    }
    asm volatile("cp.async.commit_group;");
    asm volatile("cp.async.wait_group 0;");
    __syncthreads();

    // ---- lfc GEMM: 2 k-tiles from smem ----
    float acc2[4][4][4];
#pragma unroll
    for (int i = 0; i < 4; i++)
#pragma unroll
        for (int j = 0; j < 4; j++)
#pragma unroll
            for (int q = 0; q < 4; q++) acc2[i][j][q] = 0.f;
#pragma unroll
    for (int kt = 0; kt < 2; kt++)
        mma_tile(sbase + (uint32_t)kt * TILE_B, sbase + B_AREA + (uint32_t)kt * TILE_B,
                 acc2, wm, wn, quad, lrow);

    // ---- epilogue to xcat[:,128:256] (ldc = 256) ----
#pragma unroll
    for (int im = 0; im < 4; im++) {
        int gm0 = bm + wm * 64 + im * 16 + r;
#pragma unroll
        for (int in = 0; in < 4; in++) {
            int gn = wn * 32 + in * 8 + c * 2;
            float b0 = lfc_b[gn], b1 = lfc_b[gn + 1];
            float v0 = acc2[im][in][0] + b0;
            float v1 = acc2[im][in][1] + b1;
            float v2 = acc2[im][in][2] + b0;
            float v3 = acc2[im][in][3] + b1;
            if (gm0 < M) {
                __nv_bfloat162 p = __floats2bfloat162_rn(v0, v1);
                *reinterpret_cast<uint32_t*>(xcat + (size_t)gm0 * 256 + 128 + gn) =
                    *reinterpret_cast<uint32_t*>(&p);
            }
            if (gm0 + 8 < M) {
                __nv_bfloat162 p = __floats2bfloat162_rn(v2, v3);
                *reinterpret_cast<uint32_t*>(xcat + (size_t)(gm0 + 8) * 256 + 128 + gn) =
                    *reinterpret_cast<uint32_t*>(&p);
            }
        }
    }
}

// final: out = v + 0.1*tanh(g_s + b4)
__global__ void k_final(const float* __restrict__ v, const float* __restrict__ b4,
                        float* __restrict__ out) {
    int i = blockIdx.x * blockDim.x + threadIdx.x;
    if (i >= NV * 3) return;
    out[i] = v[i] + 0.1f * tanhf(g_s[i] + b4[i % 3]);
}

// ---------------- launch ----------------------------------------------------
extern "C" void kernel_launch(void* const* d_in, const int* in_sizes, int n_in,
                              void* d_out, int out_size) {
    const float* v      = (const float*)d_in[0];
    const int*   f      = (const int*)d_in[1];
    const float* volume = (const float*)d_in[2];
    const float* fc1_w  = (const float*)d_in[3];
    const float* fc1_b  = (const float*)d_in[4];
    const float* fc2_w  = (const float*)d_in[5];
    const float* fc2_b  = (const float*)d_in[6];
    const float* fc3_w  = (const float*)d_in[7];
    const float* fc3_b  = (const float*)d_in[8];
    const float* fc4_w  = (const float*)d_in[9];
    const float* fc4_b  = (const float*)d_in[10];
    const float* conv_w = (const float*)d_in[11];
    const float* conv_b = (const float*)d_in[12];
    const float* lfc_w  = (const float*)d_in[13];
    const float* lfc_b  = (const float*)d_in[14];
    float* out = (float*)d_out;

    float *p_nrm, *p_s, *p_vol1, *p_vol2;
    bf16 *p_cubes, *p_xcat, *p_h2, *p_wconv, *p_wlfc, *p_w2, *p_w3;
    cudaGetSymbolAddress((void**)&p_nrm, g_nrm);
    cudaGetSymbolAddress((void**)&p_s, g_s);
    cudaGetSymbolAddress((void**)&p_vol1, g_vol1);
    cudaGetSymbolAddress((void**)&p_vol2, g_vol2);
    cudaGetSymbolAddress((void**)&p_cubes, g_cubes);
    cudaGetSymbolAddress((void**)&p_xcat, g_xcat);
    cudaGetSymbolAddress((void**)&p_h2, g_h2);
    cudaGetSymbolAddress((void**)&p_wconv, g_wconv);
    cudaGetSymbolAddress((void**)&p_wlfc, g_wlfc);
    cudaGetSymbolAddress((void**)&p_w2, g_w2);
    cudaGetSymbolAddress((void**)&p_w3, g_w3);

    cudaFuncSetAttribute((const void*)gemm_bf<1, 0>, cudaFuncAttributeMaxDynamicSharedMemorySize, GEMM_SMEM);
    cudaFuncSetAttribute((const void*)gemm_bf<1, 1>, cudaFuncAttributeMaxDynamicSharedMemorySize, GEMM_SMEM);
    cudaFuncSetAttribute((const void*)k_convlfc, cudaFuncAttributeMaxDynamicSharedMemorySize, GEMM_SMEM);

    // 1. zero staging + normals
    k_zero<<<(NV * 3 + 255) / 256, 256>>>(p_nrm, NV * 3);
    k_zero<<<(NV * 3 + 255) / 256, 256>>>(p_s, NV * 3);
    k_face_normals<<<(NFACE + 255) / 256, 256>>>(v, f);

    // 2. volume pyramid
    k_down<<<(L1 * L1 * L1 + 255) / 256, 256>>>(volume, p_vol1, L1);
    k_down<<<(L2DIM * L2DIM * L2DIM + 255) / 256, 256>>>(p_vol1, p_vol2, L2DIM);

    // 3. merged weight prep
    k_prep<<<(PREP_N3 + 255) / 256, 256>>>(conv_w, lfc_w, fc2_w, fc3_w);

    // 4. fc1 -> xcat[:, 0:128]
    k_fc1<<<1184, 128>>>(v, fc1_w, fc1_b);

    // 5. cube gather -> g_cubes [NV x 384] bf16
    k_gather<<<(NV + 1) / 2, 256>>>(v, volume);

    const int MB = (NV + 127) / 128;

    // 6+7. fused conv + lfc -> xcat[:, 128:256]
    k_convlfc<<<dim3(1, MB), 256, GEMM_SMEM>>>(p_cubes, p_wconv, conv_b,
                                               p_wlfc, lfc_b, p_xcat, NV);
    // 8. fc2: xcat[NV,256] @ w2^T + b, leaky -> h2 [NV,512]
    gemm_bf<1, 0><<<dim3(4, MB), 256, GEMM_SMEM>>>(p_xcat, p_w2, fc2_b, p_h2,
                                                   NV, 512, 256, 512, nullptr, nullptr);
    // 9. fc3 (+fused fc4): h2 @ w3^T + b, leaky, reduce vs fc4_w -> g_s
    gemm_bf<1, 1><<<dim3(2, MB), 256, GEMM_SMEM>>>(p_h2, p_w3, fc3_b, nullptr,
                                                   NV, 256, 512, 0, fc4_w, p_s);
    // 10. final tanh + coord add
    k_final<<<(NV * 3 + 255) / 256, 256>>>(v, fc4_b, out);
}